// round 3
// baseline (speedup 1.0000x reference)
#include <cuda_runtime.h>
#include <math.h>

#define BB   4
#define TT   2048
#define HIDD 2048
#define NHH  16
#define HDD  128
#define MTOT (BB*TT)      // 8192
#define NQKV (3*HIDD)     // 6144

#define SCALE 0.08838834764831845f   // 1/sqrt(128)

// Scratch (allocation-free: device globals)
__device__ float g_q[BB*NHH*TT*HDD];
__device__ float g_k[BB*NHH*TT*HDD];
__device__ float g_v[BB*NHH*TT*HDD];
__device__ float g_attn[BB*TT*HIDD];

// ---------------------------------------------------------------------------
// SGEMM: C[M,N] = A[M,K] * W[N,K]^T   (K = HIDD = 2048)
// MODE 0: A = x, W = w_qkv  -> epilogue: RoPE(q,k) + q*=scale, scatter to
//         g_q/g_k/g_v in [b][h][t][d] layout. One block = one (sel,head).
// MODE 1: A = g_attn, W = w_proj -> epilogue: + bias, write d_out.
// ---------------------------------------------------------------------------
template<int MODE>
__global__ __launch_bounds__(256, 2)
void gemm_kernel(const float* __restrict__ A, const float* __restrict__ W,
                 const float* __restrict__ cosb, const float* __restrict__ sinb,
                 const float* __restrict__ bias, float* __restrict__ Cout)
{
    __shared__ float As[16][132];
    __shared__ float Bs[16][132];

    const int tid = threadIdx.x;
    const int ty  = tid >> 4;       // 0..15
    const int tx  = tid & 15;       // 0..15
    const int bm  = blockIdx.y << 7;
    const int bn  = blockIdx.x << 7;

    const int lr = tid >> 2;        // 0..63  (row within tile)
    const int lc = (tid & 3) << 2;  // 0,4,8,12 (k within chunk)

    const float* Abase = (MODE == 0) ? A : (const float*)g_attn;
    const float* Ap = Abase + (size_t)(bm + lr) * HIDD + lc;
    const float* Bp = W     + (size_t)(bn + lr) * HIDD + lc;

    float acc[8][8];
#pragma unroll
    for (int i = 0; i < 8; i++)
#pragma unroll
        for (int j = 0; j < 8; j++) acc[i][j] = 0.f;

    // register prefetch of first chunk
    float4 pa0 = *(const float4*)(Ap);
    float4 pa1 = *(const float4*)(Ap + 64 * HIDD);
    float4 pb0 = *(const float4*)(Bp);
    float4 pb1 = *(const float4*)(Bp + 64 * HIDD);

    for (int k0 = 0; k0 < HIDD; k0 += 16) {
#pragma unroll
        for (int i = 0; i < 4; i++) {
            As[lc + i][lr]      = ((const float*)&pa0)[i];
            As[lc + i][lr + 64] = ((const float*)&pa1)[i];
            Bs[lc + i][lr]      = ((const float*)&pb0)[i];
            Bs[lc + i][lr + 64] = ((const float*)&pb1)[i];
        }
        __syncthreads();
        if (k0 + 16 < HIDD) {   // prefetch next chunk while computing
            pa0 = *(const float4*)(Ap + k0 + 16);
            pa1 = *(const float4*)(Ap + 64 * HIDD + k0 + 16);
            pb0 = *(const float4*)(Bp + k0 + 16);
            pb1 = *(const float4*)(Bp + 64 * HIDD + k0 + 16);
        }
#pragma unroll
        for (int kk = 0; kk < 16; kk++) {
            float4 a0 = *(const float4*)&As[kk][ty << 2];
            float4 a1 = *(const float4*)&As[kk][(ty << 2) + 64];
            float4 b0 = *(const float4*)&Bs[kk][tx << 2];
            float4 b1 = *(const float4*)&Bs[kk][(tx << 2) + 64];
            float av[8] = {a0.x, a0.y, a0.z, a0.w, a1.x, a1.y, a1.z, a1.w};
            float bv[8] = {b0.x, b0.y, b0.z, b0.w, b1.x, b1.y, b1.z, b1.w};
#pragma unroll
            for (int i = 0; i < 8; i++)
#pragma unroll
                for (int j = 0; j < 8; j++)
                    acc[i][j] += av[i] * bv[j];
        }
        __syncthreads();
    }

    if (MODE == 0) {
        // this 128-col block is exactly one (sel, head): HID%128==0, HD==128
        const int sel = bn >> 11;            // 0:q 1:k 2:v
        const int h   = (bn & 2047) >> 7;
        float* dst = (sel == 0) ? g_q : (sel == 1) ? g_k : g_v;
        const float sc = (sel == 0) ? SCALE : 1.f;
#pragma unroll
        for (int i = 0; i < 8; i++) {
            int m = bm + (ty << 2) + (i & 3) + ((i >> 2) << 6);
            int b = m >> 11;                 // / T
            int t = m & 2047;
#pragma unroll
            for (int jh = 0; jh < 2; jh++) {
                int d0 = (tx << 2) + (jh << 6);   // 4-aligned head dim
                float v0 = acc[i][jh * 4 + 0], v1 = acc[i][jh * 4 + 1];
                float v2 = acc[i][jh * 4 + 2], v3 = acc[i][jh * 4 + 3];
                if (sel < 2) {
                    int i0 = d0 >> 1;             // rope pair index
                    float c0 = cosb[t * 64 + i0],     s0 = sinb[t * 64 + i0];
                    float c1 = cosb[t * 64 + i0 + 1], s1 = sinb[t * 64 + i0 + 1];
                    float r0 = (v0 * c0 - v1 * s0) * sc;
                    float r1 = (v0 * s0 + v1 * c0) * sc;
                    float r2 = (v2 * c1 - v3 * s1) * sc;
                    float r3 = (v2 * s1 + v3 * c1) * sc;
                    v0 = r0; v1 = r1; v2 = r2; v3 = r3;
                }
                *(float4*)&dst[((b * NHH + h) * TT + t) * HDD + d0] =
                    make_float4(v0, v1, v2, v3);
            }
        }
    } else {
#pragma unroll
        for (int i = 0; i < 8; i++) {
            int m = bm + (ty << 2) + (i & 3) + ((i >> 2) << 6);
#pragma unroll
            for (int jh = 0; jh < 2; jh++) {
                int n = bn + (tx << 2) + (jh << 6);
                *(float4*)&Cout[(size_t)m * HIDD + n] =
                    make_float4(acc[i][jh * 4 + 0] + bias[n],
                                acc[i][jh * 4 + 1] + bias[n + 1],
                                acc[i][jh * 4 + 2] + bias[n + 2],
                                acc[i][jh * 4 + 3] + bias[n + 3]);
            }
        }
    }
}

// ---------------------------------------------------------------------------
// Flash attention, fp32. One block = one head x 64-query tile.
// Q pre-scaled by 1/sqrt(HD) in the QKV epilogue.
// ---------------------------------------------------------------------------
#define ATTN_SMEM_FLOATS (3*64*132 + 64*68 + 192)
#define ATTN_SMEM (ATTN_SMEM_FLOATS * 4)

__global__ __launch_bounds__(256)
void attn_kernel()
{
    extern __shared__ float sm[];
    float (*Qs)[132] = (float(*)[132])(sm);
    float (*Ks)[132] = (float(*)[132])(sm + 64 * 132);
    float (*Vs)[132] = (float(*)[132])(sm + 2 * 64 * 132);
    float (*Ss)[68]  = (float(*)[68])(sm + 3 * 64 * 132);
    float* m_s  = sm + 3 * 64 * 132 + 64 * 68;
    float* l_s  = m_s + 64;
    float* al_s = l_s + 64;

    const int tid = threadIdx.x;
    const int ty  = tid >> 4;
    const int tx  = tid & 15;
    const int bh  = blockIdx.y;                  // b*NH + h
    const size_t base = (size_t)bh * TT * HDD;
    const int q0  = blockIdx.x << 6;

    for (int i = tid; i < 64 * 32; i += 256) {   // Q tile: 64 x 128
        int r = i >> 5, c = (i & 31) << 2;
        *(float4*)&Qs[r][c] = *(const float4*)&g_q[base + (size_t)(q0 + r) * HDD + c];
    }
    if (tid < 64) { m_s[tid] = -1e30f; l_s[tid] = 0.f; }

    float oacc[4][8];
#pragma unroll
    for (int i = 0; i < 4; i++)
#pragma unroll
        for (int j = 0; j < 8; j++) oacc[i][j] = 0.f;

    for (int kt = 0; kt < TT / 64; kt++) {
        __syncthreads();                         // prev PV done with Vs/Ss
        const int k0 = kt << 6;
        for (int i = tid; i < 64 * 32; i += 256) {
            int r = i >> 5, c = (i & 31) << 2;
            *(float4*)&Ks[r][c] = *(const float4*)&g_k[base + (size_t)(k0 + r) * HDD + c];
            *(float4*)&Vs[r][c] = *(const float4*)&g_v[base + (size_t)(k0 + r) * HDD + c];
        }
        __syncthreads();

        // S = Q * K^T  (64x64), 4x4 per thread
        float s[4][4];
#pragma unroll
        for (int i = 0; i < 4; i++)
#pragma unroll
            for (int j = 0; j < 4; j++) s[i][j] = 0.f;

#pragma unroll 4
        for (int kk = 0; kk < HDD; kk += 4) {
            float4 qa[4], kb[4];
#pragma unroll
            for (int i = 0; i < 4; i++) qa[i] = *(const float4*)&Qs[(ty << 2) + i][kk];
#pragma unroll
            for (int j = 0; j < 4; j++) kb[j] = *(const float4*)&Ks[(tx << 2) + j][kk];
#pragma unroll
            for (int i = 0; i < 4; i++)
#pragma unroll
                for (int j = 0; j < 4; j++) {
                    s[i][j] += qa[i].x * kb[j].x;
                    s[i][j] += qa[i].y * kb[j].y;
                    s[i][j] += qa[i].z * kb[j].z;
                    s[i][j] += qa[i].w * kb[j].w;
                }
        }
#pragma unroll
        for (int i = 0; i < 4; i++)
#pragma unroll
            for (int j = 0; j < 4; j++)
                Ss[(ty << 2) + i][(tx << 2) + j] = s[i][j];
        __syncthreads();

        // online softmax: 4 lanes per row (256 threads cover 64 rows)
        {
            const int row = tid >> 2;
            const int cb  = (tid & 3) << 4;
            float mx = -1e30f;
#pragma unroll
            for (int c = 0; c < 16; c++) mx = fmaxf(mx, Ss[row][cb + c]);
            mx = fmaxf(mx, __shfl_xor_sync(0xffffffffu, mx, 1));
            mx = fmaxf(mx, __shfl_xor_sync(0xffffffffu, mx, 2));
            const float mold = m_s[row];
            const float mnew = fmaxf(mold, mx);
            float sum = 0.f;
#pragma unroll
            for (int c = 0; c < 16; c++) {
                float p = __expf(Ss[row][cb + c] - mnew);
                Ss[row][cb + c] = p;
                sum += p;
            }
            sum += __shfl_xor_sync(0xffffffffu, sum, 1);
            sum += __shfl_xor_sync(0xffffffffu, sum, 2);
            if ((tid & 3) == 0) {
                float alpha = __expf(mold - mnew);
                m_s[row]  = mnew;
                l_s[row]  = l_s[row] * alpha + sum;
                al_s[row] = alpha;
            }
        }
        __syncthreads();

        // rescale + O += P * V  (4 rows x 8 cols per thread)
        float al[4];
#pragma unroll
        for (int i = 0; i < 4; i++) al[i] = al_s[(ty << 2) + i];
#pragma unroll
        for (int i = 0; i < 4; i++)
#pragma unroll
            for (int j = 0; j < 8; j++) oacc[i][j] *= al[i];

#pragma unroll 2
        for (int kk = 0; kk < 64; kk += 4) {
            float pf[4][4];
#pragma unroll
            for (int i = 0; i < 4; i++) {
                float4 pv = *(const float4*)&Ss[(ty << 2) + i][kk];
                pf[i][0] = pv.x; pf[i][1] = pv.y; pf[i][2] = pv.z; pf[i][3] = pv.w;
            }
#pragma unroll
            for (int q = 0; q < 4; q++) {
                float4 va = *(const float4*)&Vs[kk + q][tx << 3];
                float4 vb = *(const float4*)&Vs[kk + q][(tx << 3) + 4];
#pragma unroll
                for (int i = 0; i < 4; i++) {
                    float p = pf[i][q];
                    oacc[i][0] += p * va.x;
                    oacc[i][1] += p * va.y;
                    oacc[i][2] += p * va.z;
                    oacc[i][3] += p * va.w;
                    oacc[i][4] += p * vb.x;
                    oacc[i][5] += p * vb.y;
                    oacc[i][6] += p * vb.z;
                    oacc[i][7] += p * vb.w;
                }
            }
        }
    }

    // normalize + write to [b][t][hid] layout for the proj GEMM
    {
        const int b = bh >> 4;
        const int h = bh & 15;
#pragma unroll
        for (int i = 0; i < 4; i++) {
            int r = (ty << 2) + i;
            int t = q0 + r;
            float inv = 1.f / l_s[r];
            int idx = (b * TT + t) * HIDD + h * HDD + (tx << 3);
            *(float4*)&g_attn[idx] =
                make_float4(oacc[i][0] * inv, oacc[i][1] * inv,
                            oacc[i][2] * inv, oacc[i][3] * inv);
            *(float4*)&g_attn[idx + 4] =
                make_float4(oacc[i][4] * inv, oacc[i][5] * inv,
                            oacc[i][6] * inv, oacc[i][7] * inv);
        }
    }
}

// ---------------------------------------------------------------------------
extern "C" void kernel_launch(void* const* d_in, const int* in_sizes, int n_in,
                              void* d_out, int out_size)
{
    (void)in_sizes; (void)n_in; (void)out_size;
    const float* x      = (const float*)d_in[0];
    const float* w_qkv  = (const float*)d_in[1];
    const float* w_proj = (const float*)d_in[2];
    const float* b_proj = (const float*)d_in[3];
    const float* cosb   = (const float*)d_in[4];
    const float* sinb   = (const float*)d_in[5];
    float* out = (float*)d_out;

    cudaFuncSetAttribute(attn_kernel,
                         cudaFuncAttributeMaxDynamicSharedMemorySize, ATTN_SMEM);

    dim3 blk(256);
    dim3 g0(NQKV / 128, MTOT / 128);          // 48 x 64
    gemm_kernel<0><<<g0, blk>>>(x, w_qkv, cosb, sinb, nullptr, nullptr);

    dim3 ga(TT / 64, BB * NHH);               // 32 x 64
    attn_kernel<<<ga, blk, ATTN_SMEM>>>();

    dim3 g1(HIDD / 128, MTOT / 128);          // 16 x 64
    gemm_kernel<1><<<g1, blk>>>(nullptr, w_proj, nullptr, nullptr, b_proj, out);
}

// round 4
// speedup vs baseline: 2.5560x; 2.5560x over previous
#include <cuda_runtime.h>
#include <math.h>
#include <stdint.h>

#define BB   4
#define TT   2048
#define HIDD 2048
#define NHH  16
#define HDD  128
#define MTOT (BB*TT)      // 8192
#define NQKV (3*HIDD)     // 6144

#define SCALE 0.08838834764831845f   // 1/sqrt(128)

// Scratch (allocation-free: device globals)
__device__ float g_q[BB*NHH*TT*HDD];
__device__ float g_k[BB*NHH*TT*HDD];
__device__ float g_v[BB*NHH*TT*HDD];
__device__ float g_attn[BB*TT*HIDD];

// ---------------------------------------------------------------------------
// tf32 helpers
// ---------------------------------------------------------------------------
__device__ __forceinline__ uint32_t f2tf(float f) {
    uint32_t u;
    asm("cvt.rna.tf32.f32 %0, %1;" : "=r"(u) : "f"(f));
    return u;
}

__device__ __forceinline__ void mma_tf32(float* c, const uint32_t* a, const uint32_t* b) {
    asm volatile(
        "mma.sync.aligned.m16n8k8.row.col.f32.tf32.tf32.f32 "
        "{%0,%1,%2,%3}, {%4,%5,%6,%7}, {%8,%9}, {%0,%1,%2,%3};\n"
        : "+f"(c[0]), "+f"(c[1]), "+f"(c[2]), "+f"(c[3])
        : "r"(a[0]), "r"(a[1]), "r"(a[2]), "r"(a[3]), "r"(b[0]), "r"(b[1]));
}

// ---------------------------------------------------------------------------
// tf32 GEMM: C[M,N] = A[M,K] * W[N,K]^T   (K = HIDD)
// MODE 0: A=x, W=w_qkv -> RoPE + scale epilogue, scatter to g_q/g_k/g_v.
// MODE 1: A=g_attn, W=w_proj -> +bias, write out.
// Block 128x128, 8 warps (2x4), each warp 64x32 = 4x4 m16n8k8 atoms.
// ---------------------------------------------------------------------------
#define KST 20   // smem k-stride (pad 16 -> 20: bank = (4r+c)%32, conflict-free)

template<int MODE>
__global__ __launch_bounds__(256, 2)
void gemm_tf32(const float* __restrict__ A, const float* __restrict__ W,
               const float* __restrict__ cosb, const float* __restrict__ sinb,
               const float* __restrict__ bias, float* __restrict__ Cout)
{
    __shared__ uint32_t As[128][KST];
    __shared__ uint32_t Bs[128][KST];

    const int tid  = threadIdx.x;
    const int w    = tid >> 5;
    const int lane = tid & 31;
    const int g    = lane >> 2;     // 0..7
    const int tg   = lane & 3;      // 0..3
    const int wm   = w >> 2;        // 0..1
    const int wn   = w & 3;         // 0..3
    const int bm   = blockIdx.y << 7;
    const int bn   = blockIdx.x << 7;

    const int lr = tid >> 2;        // 0..63
    const int lc = (tid & 3) << 2;  // 0,4,8,12

    const float* Abase = (MODE == 0) ? A : (const float*)g_attn;
    const float* Ap = Abase + (size_t)(bm + lr) * HIDD + lc;
    const float* Bp = W     + (size_t)(bn + lr) * HIDD + lc;

    float acc[4][4][4];
#pragma unroll
    for (int i = 0; i < 4; i++)
#pragma unroll
        for (int j = 0; j < 4; j++)
#pragma unroll
            for (int q = 0; q < 4; q++) acc[i][j][q] = 0.f;

    float4 pa0 = *(const float4*)(Ap);
    float4 pa1 = *(const float4*)(Ap + 64 * HIDD);
    float4 pb0 = *(const float4*)(Bp);
    float4 pb1 = *(const float4*)(Bp + 64 * HIDD);

    for (int k0 = 0; k0 < HIDD; k0 += 16) {
        *(uint4*)&As[lr][lc]      = make_uint4(f2tf(pa0.x), f2tf(pa0.y), f2tf(pa0.z), f2tf(pa0.w));
        *(uint4*)&As[lr + 64][lc] = make_uint4(f2tf(pa1.x), f2tf(pa1.y), f2tf(pa1.z), f2tf(pa1.w));
        *(uint4*)&Bs[lr][lc]      = make_uint4(f2tf(pb0.x), f2tf(pb0.y), f2tf(pb0.z), f2tf(pb0.w));
        *(uint4*)&Bs[lr + 64][lc] = make_uint4(f2tf(pb1.x), f2tf(pb1.y), f2tf(pb1.z), f2tf(pb1.w));
        __syncthreads();
        if (k0 + 16 < HIDD) {
            pa0 = *(const float4*)(Ap + k0 + 16);
            pa1 = *(const float4*)(Ap + 64 * HIDD + k0 + 16);
            pb0 = *(const float4*)(Bp + k0 + 16);
            pb1 = *(const float4*)(Bp + 64 * HIDD + k0 + 16);
        }
#pragma unroll
        for (int ka = 0; ka < 2; ka++) {
            const int kb = ka << 3;
            uint32_t af[4][4], bf[4][2];
#pragma unroll
            for (int mi = 0; mi < 4; mi++) {
                int r = wm * 64 + mi * 16 + g;
                af[mi][0] = As[r][kb + tg];
                af[mi][1] = As[r + 8][kb + tg];
                af[mi][2] = As[r][kb + tg + 4];
                af[mi][3] = As[r + 8][kb + tg + 4];
            }
#pragma unroll
            for (int ni = 0; ni < 4; ni++) {
                int c = wn * 32 + ni * 8 + g;
                bf[ni][0] = Bs[c][kb + tg];
                bf[ni][1] = Bs[c][kb + tg + 4];
            }
#pragma unroll
            for (int mi = 0; mi < 4; mi++)
#pragma unroll
                for (int ni = 0; ni < 4; ni++)
                    mma_tf32(acc[mi][ni], af[mi], bf[ni]);
        }
        __syncthreads();
    }

    if (MODE == 0) {
        const int sel = bn >> 11;            // 0:q 1:k 2:v
        const int h   = (bn & 2047) >> 7;
        float* dst = (sel == 0) ? g_q : (sel == 1) ? g_k : g_v;
        const float sc = (sel == 0) ? SCALE : 1.f;
#pragma unroll
        for (int mi = 0; mi < 4; mi++) {
#pragma unroll
            for (int ni = 0; ni < 4; ni++) {
                const int d0 = wn * 32 + ni * 8 + tg * 2;
#pragma unroll
                for (int hr = 0; hr < 2; hr++) {
                    int m = bm + wm * 64 + mi * 16 + g + hr * 8;
                    int b = m >> 11, t = m & 2047;
                    float e = acc[mi][ni][hr * 2 + 0];
                    float o = acc[mi][ni][hr * 2 + 1];
                    if (sel < 2) {
                        int i0 = d0 >> 1;
                        float c = cosb[t * 64 + i0];
                        float s = sinb[t * 64 + i0];
                        float re = (e * c - o * s) * sc;
                        float ro = (e * s + o * c) * sc;
                        e = re; o = ro;
                    }
                    *(float2*)&dst[((size_t)(b * NHH + h) * TT + t) * HDD + d0] =
                        make_float2(e, o);
                }
            }
        }
    } else {
#pragma unroll
        for (int mi = 0; mi < 4; mi++) {
#pragma unroll
            for (int ni = 0; ni < 4; ni++) {
                const int n = bn + wn * 32 + ni * 8 + tg * 2;
                const float2 bi = *(const float2*)&bias[n];
#pragma unroll
                for (int hr = 0; hr < 2; hr++) {
                    int m = bm + wm * 64 + mi * 16 + g + hr * 8;
                    *(float2*)&Cout[(size_t)m * HIDD + n] =
                        make_float2(acc[mi][ni][hr * 2 + 0] + bi.x,
                                    acc[mi][ni][hr * 2 + 1] + bi.y);
                }
            }
        }
    }
}

// ---------------------------------------------------------------------------
// Flash attention, tf32 tensor core. One block = one (b,h) x 64-query tile.
// Q pre-scaled by 1/sqrt(HD) in the QKV epilogue.
// smem (uint32 words): Q[64][132] K[64][132] V[64][132] S[64][68] m/l/al[3*64]
// ---------------------------------------------------------------------------
#define QS 132   // (4r+c)%32 pattern -> conflict-free frag LDS
#define SS 68
#define ATTN_WORDS (3*64*QS + 64*SS + 192)
#define ATTN_SMEM  (ATTN_WORDS * 4)

__global__ __launch_bounds__(256)
void attn_kernel()
{
    extern __shared__ uint32_t sm[];
    uint32_t* Qs = sm;
    uint32_t* Ks = sm + 64 * QS;
    uint32_t* Vs = sm + 2 * 64 * QS;
    uint32_t* Su = sm + 3 * 64 * QS;
    float*    Sf = (float*)Su;
    float*    m_s  = (float*)(sm + 3 * 64 * QS + 64 * SS);
    float*    l_s  = m_s + 64;
    float*    al_s = l_s + 64;

    const int tid  = threadIdx.x;
    const int w    = tid >> 5;
    const int lane = tid & 31;
    const int g    = lane >> 2;
    const int tg   = lane & 3;
    const int bh   = blockIdx.y;                // b*NH + h
    const size_t base = (size_t)bh * TT * HDD;
    const int q0   = blockIdx.x << 6;

    // S-phase warp tiles: 16 rows x 32 cols
    const int smrow = (w >> 1) << 4;
    const int scol  = (w & 1) << 5;
    // PV-phase warp tiles: 16 rows x 64 cols
    const int pvrow = smrow;
    const int pvcol = (w & 1) << 6;

    // load Q (cvt to tf32)
    for (int i = tid; i < 64 * 32; i += 256) {
        int r = i >> 5, c = (i & 31) << 2;
        float4 v = *(const float4*)&g_q[base + (size_t)(q0 + r) * HDD + c];
        *(uint4*)&Qs[r * QS + c] = make_uint4(f2tf(v.x), f2tf(v.y), f2tf(v.z), f2tf(v.w));
    }
    if (tid < 64) { m_s[tid] = -1e30f; l_s[tid] = 0.f; }

    float oacc[8][4];
#pragma unroll
    for (int i = 0; i < 8; i++)
#pragma unroll
        for (int j = 0; j < 4; j++) oacc[i][j] = 0.f;

    for (int kt = 0; kt < TT / 64; kt++) {
        __syncthreads();                         // prev PV done with Vs/Su
        const int k0 = kt << 6;
        for (int i = tid; i < 64 * 32; i += 256) {
            int r = i >> 5, c = (i & 31) << 2;
            float4 kv = *(const float4*)&g_k[base + (size_t)(k0 + r) * HDD + c];
            float4 vv = *(const float4*)&g_v[base + (size_t)(k0 + r) * HDD + c];
            *(uint4*)&Ks[r * QS + c] = make_uint4(f2tf(kv.x), f2tf(kv.y), f2tf(kv.z), f2tf(kv.w));
            *(uint4*)&Vs[r * QS + c] = make_uint4(f2tf(vv.x), f2tf(vv.y), f2tf(vv.z), f2tf(vv.w));
        }
        __syncthreads();

        // S = Q*K^T : per warp 1x4 atoms, k-atoms over 128
        float sacc[4][4];
#pragma unroll
        for (int ni = 0; ni < 4; ni++)
#pragma unroll
            for (int q = 0; q < 4; q++) sacc[ni][q] = 0.f;

#pragma unroll
        for (int ka = 0; ka < 16; ka++) {
            const int kb = ka << 3;
            uint32_t aq[4];
            aq[0] = Qs[(smrow + g) * QS + kb + tg];
            aq[1] = Qs[(smrow + g + 8) * QS + kb + tg];
            aq[2] = Qs[(smrow + g) * QS + kb + tg + 4];
            aq[3] = Qs[(smrow + g + 8) * QS + kb + tg + 4];
#pragma unroll
            for (int ni = 0; ni < 4; ni++) {
                uint32_t bk[2];
                int c = scol + ni * 8 + g;
                bk[0] = Ks[c * QS + kb + tg];
                bk[1] = Ks[c * QS + kb + tg + 4];
                mma_tf32(sacc[ni], aq, bk);
            }
        }
        // write raw scores (fp32)
#pragma unroll
        for (int ni = 0; ni < 4; ni++) {
            int cc = scol + ni * 8 + tg * 2;
            *(float2*)&Sf[(smrow + g) * SS + cc]     = make_float2(sacc[ni][0], sacc[ni][1]);
            *(float2*)&Sf[(smrow + g + 8) * SS + cc] = make_float2(sacc[ni][2], sacc[ni][3]);
        }
        __syncthreads();

        // online softmax: 4 lanes per row; store exp() pre-converted to tf32
        {
            const int row = tid >> 2;
            const int cb  = (tid & 3) << 4;
            float mx = -1e30f;
#pragma unroll
            for (int c = 0; c < 16; c++) mx = fmaxf(mx, Sf[row * SS + cb + c]);
            mx = fmaxf(mx, __shfl_xor_sync(0xffffffffu, mx, 1));
            mx = fmaxf(mx, __shfl_xor_sync(0xffffffffu, mx, 2));
            const float mold = m_s[row];
            const float mnew = fmaxf(mold, mx);
            float sum = 0.f;
#pragma unroll
            for (int c = 0; c < 16; c++) {
                float p = __expf(Sf[row * SS + cb + c] - mnew);
                Su[row * SS + cb + c] = f2tf(p);
                sum += p;
            }
            sum += __shfl_xor_sync(0xffffffffu, sum, 1);
            sum += __shfl_xor_sync(0xffffffffu, sum, 2);
            if ((tid & 3) == 0) {
                float alpha = __expf(mold - mnew);
                m_s[row]  = mnew;
                l_s[row]  = l_s[row] * alpha + sum;
                al_s[row] = alpha;
            }
        }
        __syncthreads();

        // O = O*alpha + P*V : per warp 1x8 atoms, k-atoms over 64 keys
        const float a0 = al_s[pvrow + g];
        const float a1 = al_s[pvrow + g + 8];
#pragma unroll
        for (int ni = 0; ni < 8; ni++) {
            oacc[ni][0] *= a0; oacc[ni][1] *= a0;
            oacc[ni][2] *= a1; oacc[ni][3] *= a1;
        }
#pragma unroll
        for (int ka = 0; ka < 8; ka++) {
            const int kb = ka << 3;
            uint32_t ap[4];
            ap[0] = Su[(pvrow + g) * SS + kb + tg];
            ap[1] = Su[(pvrow + g + 8) * SS + kb + tg];
            ap[2] = Su[(pvrow + g) * SS + kb + tg + 4];
            ap[3] = Su[(pvrow + g + 8) * SS + kb + tg + 4];
#pragma unroll
            for (int ni = 0; ni < 8; ni++) {
                uint32_t bv[2];
                int n = pvcol + ni * 8 + g;
                bv[0] = Vs[(kb + tg) * QS + n];
                bv[1] = Vs[(kb + tg + 4) * QS + n];
                mma_tf32(oacc[ni], ap, bv);
            }
        }
    }

    // normalize + write to [b][t][hid] layout for proj
    {
        const int b = bh >> 4;
        const int h = bh & 15;
        const int r0 = pvrow + g, r1 = r0 + 8;
        const float inv0 = 1.f / l_s[r0];
        const float inv1 = 1.f / l_s[r1];
        const int t0 = q0 + r0, t1 = q0 + r1;
#pragma unroll
        for (int ni = 0; ni < 8; ni++) {
            int d = pvcol + ni * 8 + tg * 2;
            *(float2*)&g_attn[((size_t)(b * TT + t0)) * HIDD + h * HDD + d] =
                make_float2(oacc[ni][0] * inv0, oacc[ni][1] * inv0);
            *(float2*)&g_attn[((size_t)(b * TT + t1)) * HIDD + h * HDD + d] =
                make_float2(oacc[ni][2] * inv1, oacc[ni][3] * inv1);
        }
    }
}

// ---------------------------------------------------------------------------
extern "C" void kernel_launch(void* const* d_in, const int* in_sizes, int n_in,
                              void* d_out, int out_size)
{
    (void)in_sizes; (void)n_in; (void)out_size;
    const float* x      = (const float*)d_in[0];
    const float* w_qkv  = (const float*)d_in[1];
    const float* w_proj = (const float*)d_in[2];
    const float* b_proj = (const float*)d_in[3];
    const float* cosb   = (const float*)d_in[4];
    const float* sinb   = (const float*)d_in[5];
    float* out = (float*)d_out;

    cudaFuncSetAttribute(attn_kernel,
                         cudaFuncAttributeMaxDynamicSharedMemorySize, ATTN_SMEM);

    dim3 blk(256);
    dim3 g0(NQKV / 128, MTOT / 128);          // 48 x 64
    gemm_tf32<0><<<g0, blk>>>(x, w_qkv, cosb, sinb, nullptr, nullptr);

    dim3 ga(TT / 64, BB * NHH);               // 32 x 64
    attn_kernel<<<ga, blk, ATTN_SMEM>>>();

    dim3 g1(HIDD / 128, MTOT / 128);          // 16 x 64
    gemm_tf32<1><<<g1, blk>>>(nullptr, w_proj, nullptr, nullptr, b_proj, out);
}

// round 5
// speedup vs baseline: 2.5587x; 1.0011x over previous
#include <cuda_runtime.h>
#include <math.h>
#include <stdint.h>

#define BB   4
#define TT   2048
#define HIDD 2048
#define NHH  16
#define HDD  128
#define MTOT (BB*TT)      // 8192
#define NQKV (3*HIDD)     // 6144

#define SCALE 0.08838834764831845f   // 1/sqrt(128)

// Scratch (allocation-free: device globals)
__device__ float g_q[BB*NHH*TT*HDD];
__device__ float g_k[BB*NHH*TT*HDD];
__device__ float g_v[BB*NHH*TT*HDD];
__device__ float g_attn[BB*TT*HIDD];

// ---------------------------------------------------------------------------
// tf32 helpers
// ---------------------------------------------------------------------------
__device__ __forceinline__ uint32_t f2tf(float f) {
    uint32_t u;
    asm("cvt.rna.tf32.f32 %0, %1;" : "=r"(u) : "f"(f));
    return u;
}

__device__ __forceinline__ void mma_tf32(float* c, const uint32_t* a, const uint32_t* b) {
    asm volatile(
        "mma.sync.aligned.m16n8k8.row.col.f32.tf32.tf32.f32 "
        "{%0,%1,%2,%3}, {%4,%5,%6,%7}, {%8,%9}, {%0,%1,%2,%3};\n"
        : "+f"(c[0]), "+f"(c[1]), "+f"(c[2]), "+f"(c[3])
        : "r"(a[0]), "r"(a[1]), "r"(a[2]), "r"(a[3]), "r"(b[0]), "r"(b[1]));
}

// ---------------------------------------------------------------------------
// tf32 GEMM: C[M,N] = A[M,K] * W[N,K]^T   (K = HIDD)
// MODE 0: A=x, W=w_qkv -> RoPE + scale epilogue, scatter to g_q/g_k/g_v.
// MODE 1: A=g_attn, W=w_proj -> +bias, write out.
// Block 128x128, 8 warps (2x4), each warp 64x32 = 4x4 m16n8k8 atoms.
// ---------------------------------------------------------------------------
#define KST 20   // smem k-stride (pad 16 -> 20: bank = (4r+c)%32, conflict-free)

template<int MODE>
__global__ __launch_bounds__(256, 2)
void gemm_tf32(const float* __restrict__ A, const float* __restrict__ W,
               const float* __restrict__ cosb, const float* __restrict__ sinb,
               const float* __restrict__ bias, float* __restrict__ Cout)
{
    __shared__ uint32_t As[128][KST];
    __shared__ uint32_t Bs[128][KST];

    const int tid  = threadIdx.x;
    const int w    = tid >> 5;
    const int lane = tid & 31;
    const int g    = lane >> 2;     // 0..7
    const int tg   = lane & 3;      // 0..3
    const int wm   = w >> 2;        // 0..1
    const int wn   = w & 3;         // 0..3
    const int bm   = blockIdx.y << 7;
    const int bn   = blockIdx.x << 7;

    const int lr = tid >> 2;        // 0..63
    const int lc = (tid & 3) << 2;  // 0,4,8,12

    const float* Abase = (MODE == 0) ? A : (const float*)g_attn;
    const float* Ap = Abase + (size_t)(bm + lr) * HIDD + lc;
    const float* Bp = W     + (size_t)(bn + lr) * HIDD + lc;

    float acc[4][4][4];
#pragma unroll
    for (int i = 0; i < 4; i++)
#pragma unroll
        for (int j = 0; j < 4; j++)
#pragma unroll
            for (int q = 0; q < 4; q++) acc[i][j][q] = 0.f;

    float4 pa0 = *(const float4*)(Ap);
    float4 pa1 = *(const float4*)(Ap + 64 * HIDD);
    float4 pb0 = *(const float4*)(Bp);
    float4 pb1 = *(const float4*)(Bp + 64 * HIDD);

    for (int k0 = 0; k0 < HIDD; k0 += 16) {
        *(uint4*)&As[lr][lc]      = make_uint4(f2tf(pa0.x), f2tf(pa0.y), f2tf(pa0.z), f2tf(pa0.w));
        *(uint4*)&As[lr + 64][lc] = make_uint4(f2tf(pa1.x), f2tf(pa1.y), f2tf(pa1.z), f2tf(pa1.w));
        *(uint4*)&Bs[lr][lc]      = make_uint4(f2tf(pb0.x), f2tf(pb0.y), f2tf(pb0.z), f2tf(pb0.w));
        *(uint4*)&Bs[lr + 64][lc] = make_uint4(f2tf(pb1.x), f2tf(pb1.y), f2tf(pb1.z), f2tf(pb1.w));
        __syncthreads();
        if (k0 + 16 < HIDD) {
            pa0 = *(const float4*)(Ap + k0 + 16);
            pa1 = *(const float4*)(Ap + 64 * HIDD + k0 + 16);
            pb0 = *(const float4*)(Bp + k0 + 16);
            pb1 = *(const float4*)(Bp + 64 * HIDD + k0 + 16);
        }
#pragma unroll
        for (int ka = 0; ka < 2; ka++) {
            const int kb = ka << 3;
            uint32_t af[4][4], bf[4][2];
#pragma unroll
            for (int mi = 0; mi < 4; mi++) {
                int r = wm * 64 + mi * 16 + g;
                af[mi][0] = As[r][kb + tg];
                af[mi][1] = As[r + 8][kb + tg];
                af[mi][2] = As[r][kb + tg + 4];
                af[mi][3] = As[r + 8][kb + tg + 4];
            }
#pragma unroll
            for (int ni = 0; ni < 4; ni++) {
                int c = wn * 32 + ni * 8 + g;
                bf[ni][0] = Bs[c][kb + tg];
                bf[ni][1] = Bs[c][kb + tg + 4];
            }
#pragma unroll
            for (int mi = 0; mi < 4; mi++)
#pragma unroll
                for (int ni = 0; ni < 4; ni++)
                    mma_tf32(acc[mi][ni], af[mi], bf[ni]);
        }
        __syncthreads();
    }

    if (MODE == 0) {
        const int sel = bn >> 11;            // 0:q 1:k 2:v
        const int h   = (bn & 2047) >> 7;
        float* dst = (sel == 0) ? g_q : (sel == 1) ? g_k : g_v;
        const float sc = (sel == 0) ? SCALE : 1.f;
#pragma unroll
        for (int mi = 0; mi < 4; mi++) {
#pragma unroll
            for (int ni = 0; ni < 4; ni++) {
                const int d0 = wn * 32 + ni * 8 + tg * 2;
#pragma unroll
                for (int hr = 0; hr < 2; hr++) {
                    int m = bm + wm * 64 + mi * 16 + g + hr * 8;
                    int b = m >> 11, t = m & 2047;
                    float e = acc[mi][ni][hr * 2 + 0];
                    float o = acc[mi][ni][hr * 2 + 1];
                    if (sel < 2) {
                        int i0 = d0 >> 1;
                        float c = cosb[t * 64 + i0];
                        float s = sinb[t * 64 + i0];
                        float re = (e * c - o * s) * sc;
                        float ro = (e * s + o * c) * sc;
                        e = re; o = ro;
                    }
                    *(float2*)&dst[((size_t)(b * NHH + h) * TT + t) * HDD + d0] =
                        make_float2(e, o);
                }
            }
        }
    } else {
#pragma unroll
        for (int mi = 0; mi < 4; mi++) {
#pragma unroll
            for (int ni = 0; ni < 4; ni++) {
                const int n = bn + wn * 32 + ni * 8 + tg * 2;
                const float2 bi = *(const float2*)&bias[n];
#pragma unroll
                for (int hr = 0; hr < 2; hr++) {
                    int m = bm + wm * 64 + mi * 16 + g + hr * 8;
                    *(float2*)&Cout[(size_t)m * HIDD + n] =
                        make_float2(acc[mi][ni][hr * 2 + 0] + bi.x,
                                    acc[mi][ni][hr * 2 + 1] + bi.y);
                }
            }
        }
    }
}

// ---------------------------------------------------------------------------
// Flash attention, tf32 tensor core. One block = one (b,h) x 64-query tile.
// Q pre-scaled by 1/sqrt(HD) in the QKV epilogue.
// smem (uint32 words): Q[64][132] K[64][132] V[64][132] S[64][68] m/l/al[3*64]
// ---------------------------------------------------------------------------
#define QS 132   // (4r+c)%32 pattern -> conflict-free frag LDS
#define SS 68
#define ATTN_WORDS (3*64*QS + 64*SS + 192)
#define ATTN_SMEM  (ATTN_WORDS * 4)

__global__ __launch_bounds__(256)
void attn_kernel()
{
    extern __shared__ uint32_t sm[];
    uint32_t* Qs = sm;
    uint32_t* Ks = sm + 64 * QS;
    uint32_t* Vs = sm + 2 * 64 * QS;
    uint32_t* Su = sm + 3 * 64 * QS;
    float*    Sf = (float*)Su;
    float*    m_s  = (float*)(sm + 3 * 64 * QS + 64 * SS);
    float*    l_s  = m_s + 64;
    float*    al_s = l_s + 64;

    const int tid  = threadIdx.x;
    const int w    = tid >> 5;
    const int lane = tid & 31;
    const int g    = lane >> 2;
    const int tg   = lane & 3;
    const int bh   = blockIdx.y;                // b*NH + h
    const size_t base = (size_t)bh * TT * HDD;
    const int q0   = blockIdx.x << 6;

    // S-phase warp tiles: 16 rows x 32 cols
    const int smrow = (w >> 1) << 4;
    const int scol  = (w & 1) << 5;
    // PV-phase warp tiles: 16 rows x 64 cols
    const int pvrow = smrow;
    const int pvcol = (w & 1) << 6;

    // load Q (cvt to tf32)
    for (int i = tid; i < 64 * 32; i += 256) {
        int r = i >> 5, c = (i & 31) << 2;
        float4 v = *(const float4*)&g_q[base + (size_t)(q0 + r) * HDD + c];
        *(uint4*)&Qs[r * QS + c] = make_uint4(f2tf(v.x), f2tf(v.y), f2tf(v.z), f2tf(v.w));
    }
    if (tid < 64) { m_s[tid] = -1e30f; l_s[tid] = 0.f; }

    float oacc[8][4];
#pragma unroll
    for (int i = 0; i < 8; i++)
#pragma unroll
        for (int j = 0; j < 4; j++) oacc[i][j] = 0.f;

    for (int kt = 0; kt < TT / 64; kt++) {
        __syncthreads();                         // prev PV done with Vs/Su
        const int k0 = kt << 6;
        for (int i = tid; i < 64 * 32; i += 256) {
            int r = i >> 5, c = (i & 31) << 2;
            float4 kv = *(const float4*)&g_k[base + (size_t)(k0 + r) * HDD + c];
            float4 vv = *(const float4*)&g_v[base + (size_t)(k0 + r) * HDD + c];
            *(uint4*)&Ks[r * QS + c] = make_uint4(f2tf(kv.x), f2tf(kv.y), f2tf(kv.z), f2tf(kv.w));
            *(uint4*)&Vs[r * QS + c] = make_uint4(f2tf(vv.x), f2tf(vv.y), f2tf(vv.z), f2tf(vv.w));
        }
        __syncthreads();

        // S = Q*K^T : per warp 1x4 atoms, k-atoms over 128
        float sacc[4][4];
#pragma unroll
        for (int ni = 0; ni < 4; ni++)
#pragma unroll
            for (int q = 0; q < 4; q++) sacc[ni][q] = 0.f;

#pragma unroll
        for (int ka = 0; ka < 16; ka++) {
            const int kb = ka << 3;
            uint32_t aq[4];
            aq[0] = Qs[(smrow + g) * QS + kb + tg];
            aq[1] = Qs[(smrow + g + 8) * QS + kb + tg];
            aq[2] = Qs[(smrow + g) * QS + kb + tg + 4];
            aq[3] = Qs[(smrow + g + 8) * QS + kb + tg + 4];
#pragma unroll
            for (int ni = 0; ni < 4; ni++) {
                uint32_t bk[2];
                int c = scol + ni * 8 + g;
                bk[0] = Ks[c * QS + kb + tg];
                bk[1] = Ks[c * QS + kb + tg + 4];
                mma_tf32(sacc[ni], aq, bk);
            }
        }
        // write raw scores (fp32)
#pragma unroll
        for (int ni = 0; ni < 4; ni++) {
            int cc = scol + ni * 8 + tg * 2;
            *(float2*)&Sf[(smrow + g) * SS + cc]     = make_float2(sacc[ni][0], sacc[ni][1]);
            *(float2*)&Sf[(smrow + g + 8) * SS + cc] = make_float2(sacc[ni][2], sacc[ni][3]);
        }
        __syncthreads();

        // online softmax: 4 lanes per row; store exp() pre-converted to tf32
        {
            const int row = tid >> 2;
            const int cb  = (tid & 3) << 4;
            float mx = -1e30f;
#pragma unroll
            for (int c = 0; c < 16; c++) mx = fmaxf(mx, Sf[row * SS + cb + c]);
            mx = fmaxf(mx, __shfl_xor_sync(0xffffffffu, mx, 1));
            mx = fmaxf(mx, __shfl_xor_sync(0xffffffffu, mx, 2));
            const float mold = m_s[row];
            const float mnew = fmaxf(mold, mx);
            float sum = 0.f;
#pragma unroll
            for (int c = 0; c < 16; c++) {
                float p = __expf(Sf[row * SS + cb + c] - mnew);
                Su[row * SS + cb + c] = f2tf(p);
                sum += p;
            }
            sum += __shfl_xor_sync(0xffffffffu, sum, 1);
            sum += __shfl_xor_sync(0xffffffffu, sum, 2);
            if ((tid & 3) == 0) {
                float alpha = __expf(mold - mnew);
                m_s[row]  = mnew;
                l_s[row]  = l_s[row] * alpha + sum;
                al_s[row] = alpha;
            }
        }
        __syncthreads();

        // O = O*alpha + P*V : per warp 1x8 atoms, k-atoms over 64 keys
        const float a0 = al_s[pvrow + g];
        const float a1 = al_s[pvrow + g + 8];
#pragma unroll
        for (int ni = 0; ni < 8; ni++) {
            oacc[ni][0] *= a0; oacc[ni][1] *= a0;
            oacc[ni][2] *= a1; oacc[ni][3] *= a1;
        }
#pragma unroll
        for (int ka = 0; ka < 8; ka++) {
            const int kb = ka << 3;
            uint32_t ap[4];
            ap[0] = Su[(pvrow + g) * SS + kb + tg];
            ap[1] = Su[(pvrow + g + 8) * SS + kb + tg];
            ap[2] = Su[(pvrow + g) * SS + kb + tg + 4];
            ap[3] = Su[(pvrow + g + 8) * SS + kb + tg + 4];
#pragma unroll
            for (int ni = 0; ni < 8; ni++) {
                uint32_t bv[2];
                int n = pvcol + ni * 8 + g;
                bv[0] = Vs[(kb + tg) * QS + n];
                bv[1] = Vs[(kb + tg + 4) * QS + n];
                mma_tf32(oacc[ni], ap, bv);
            }
        }
    }

    // normalize + write to [b][t][hid] layout for proj
    {
        const int b = bh >> 4;
        const int h = bh & 15;
        const int r0 = pvrow + g, r1 = r0 + 8;
        const float inv0 = 1.f / l_s[r0];
        const float inv1 = 1.f / l_s[r1];
        const int t0 = q0 + r0, t1 = q0 + r1;
#pragma unroll
        for (int ni = 0; ni < 8; ni++) {
            int d = pvcol + ni * 8 + tg * 2;
            *(float2*)&g_attn[((size_t)(b * TT + t0)) * HIDD + h * HDD + d] =
                make_float2(oacc[ni][0] * inv0, oacc[ni][1] * inv0);
            *(float2*)&g_attn[((size_t)(b * TT + t1)) * HIDD + h * HDD + d] =
                make_float2(oacc[ni][2] * inv1, oacc[ni][3] * inv1);
        }
    }
}

// ---------------------------------------------------------------------------
extern "C" void kernel_launch(void* const* d_in, const int* in_sizes, int n_in,
                              void* d_out, int out_size)
{
    (void)in_sizes; (void)n_in; (void)out_size;
    const float* x      = (const float*)d_in[0];
    const float* w_qkv  = (const float*)d_in[1];
    const float* w_proj = (const float*)d_in[2];
    const float* b_proj = (const float*)d_in[3];
    const float* cosb   = (const float*)d_in[4];
    const float* sinb   = (const float*)d_in[5];
    float* out = (float*)d_out;

    cudaFuncSetAttribute(attn_kernel,
                         cudaFuncAttributeMaxDynamicSharedMemorySize, ATTN_SMEM);

    dim3 blk(256);
    dim3 g0(NQKV / 128, MTOT / 128);          // 48 x 64
    gemm_tf32<0><<<g0, blk>>>(x, w_qkv, cosb, sinb, nullptr, nullptr);

    dim3 ga(TT / 64, BB * NHH);               // 32 x 64
    attn_kernel<<<ga, blk, ATTN_SMEM>>>();

    dim3 g1(HIDD / 128, MTOT / 128);          // 16 x 64
    gemm_tf32<1><<<g1, blk>>>(nullptr, w_proj, nullptr, nullptr, b_proj, out);
}

// round 7
// speedup vs baseline: 4.3561x; 1.7024x over previous
#include <cuda_runtime.h>
#include <math.h>
#include <stdint.h>

#define BB   4
#define TT   2048
#define HIDD 2048
#define NHH  16
#define HDD  128
#define MTOT (BB*TT)
#define NQKV (3*HIDD)
#define NX   (MTOT*HIDD)
#define NW1  (NQKV*HIDD)
#define NW2  (HIDD*HIDD)
#define SCALE 0.08838834764831845f

__device__ float g_q[BB*NHH*TT*HDD];
__device__ float g_k[BB*NHH*TT*HDD];
__device__ float g_v[BB*NHH*TT*HDD];
__device__ float g_attn[BB*TT*HIDD];
__device__ float g_x[NX];
__device__ float g_w1[NW1];
__device__ float g_w2[NW2];

__device__ __forceinline__ uint32_t f2tf(float f) {
    uint32_t u; asm("cvt.rna.tf32.f32 %0, %1;" : "=r"(u) : "f"(f)); return u;
}
__device__ __forceinline__ float rtf(float f) { return __uint_as_float(f2tf(f)); }

__device__ __forceinline__ void mma_tf32(float* c, const uint32_t* a, const uint32_t* b) {
    asm volatile(
        "mma.sync.aligned.m16n8k8.row.col.f32.tf32.tf32.f32 "
        "{%0,%1,%2,%3}, {%4,%5,%6,%7}, {%8,%9}, {%0,%1,%2,%3};\n"
        : "+f"(c[0]), "+f"(c[1]), "+f"(c[2]), "+f"(c[3])
        : "r"(a[0]), "r"(a[1]), "r"(a[2]), "r"(a[3]), "r"(b[0]), "r"(b[1]));
}
__device__ __forceinline__ void cp16(void* s, const void* g) {
    uint32_t sa = (uint32_t)__cvta_generic_to_shared(s);
    asm volatile("cp.async.cg.shared.global [%0], [%1], 16;" :: "r"(sa), "l"(g));
}
#define CPC    asm volatile("cp.async.commit_group;")
#define CPW(n) asm volatile("cp.async.wait_group %0;" :: "n"(n))

// ---------------- pre-round inputs to tf32 ----------------
__global__ void round_k(const float* __restrict__ in, float* __restrict__ outp) {
    int i = (blockIdx.x * 256 + threadIdx.x) * 4;
    float4 v = *(const float4*)(in + i);
    *(float4*)(outp + i) = make_float4(rtf(v.x), rtf(v.y), rtf(v.z), rtf(v.w));
}

// ---------------- tf32 GEMM, 3-stage cp.async ----------------
// MODE 0: g_x * g_w1^T -> RoPE+scale -> g_q/g_k/g_v (tf32-rounded)
// MODE 1: g_attn * g_w2^T + bias -> out (fp32)
#define GAW (128*20)
#define GEMM_SMEM (3 * 2 * GAW * 4)

template<int MODE>
__global__ __launch_bounds__(256, 2)
void gemm_tf32(const float* __restrict__ cosb, const float* __restrict__ sinb,
               const float* __restrict__ bias, float* __restrict__ Cout)
{
    extern __shared__ float gs[];
    const int tid  = threadIdx.x;
    const int w    = tid >> 5, lane = tid & 31;
    const int g    = lane >> 2, tg = lane & 3;
    const int wm   = w >> 2, wn = w & 3;
    const int bm   = blockIdx.y << 7, bn = blockIdx.x << 7;
    const int lr = tid >> 2, lc = (tid & 3) << 2;

    const float* Ap = ((MODE == 0) ? g_x  : g_attn) + (size_t)(bm + lr) * HIDD + lc;
    const float* Bp = ((MODE == 0) ? g_w1 : g_w2)   + (size_t)(bn + lr) * HIDD + lc;

    float acc[4][4][4];
#pragma unroll
    for (int i = 0; i < 4; i++)
#pragma unroll
        for (int j = 0; j < 4; j++)
#pragma unroll
            for (int q = 0; q < 4; q++) acc[i][j][q] = 0.f;

#pragma unroll
    for (int c = 0; c < 2; c++) {
        float* sA = gs + c * 2 * GAW; float* sB = sA + GAW;
        cp16(&sA[lr * 20 + lc],        Ap + c * 16);
        cp16(&sA[(lr + 64) * 20 + lc], Ap + 64 * HIDD + c * 16);
        cp16(&sB[lr * 20 + lc],        Bp + c * 16);
        cp16(&sB[(lr + 64) * 20 + lc], Bp + 64 * HIDD + c * 16);
        CPC;
    }

#pragma unroll 1
    for (int kc = 0; kc < HIDD / 16; kc++) {
        CPW(1);
        __syncthreads();
        if (kc + 2 < HIDD / 16) {
            int c = kc + 2;
            float* sA = gs + (c % 3) * 2 * GAW; float* sB = sA + GAW;
            cp16(&sA[lr * 20 + lc],        Ap + c * 16);
            cp16(&sA[(lr + 64) * 20 + lc], Ap + 64 * HIDD + c * 16);
            cp16(&sB[lr * 20 + lc],        Bp + c * 16);
            cp16(&sB[(lr + 64) * 20 + lc], Bp + 64 * HIDD + c * 16);
        }
        CPC;

        const float* sA = gs + (kc % 3) * 2 * GAW;
        const float* sB = sA + GAW;
#pragma unroll
        for (int ka = 0; ka < 2; ka++) {
            const int kb = ka << 3;
            uint32_t af[4][4], bf[4][2];
#pragma unroll
            for (int mi = 0; mi < 4; mi++) {
                int r = wm * 64 + mi * 16 + g;
                af[mi][0] = __float_as_uint(sA[r * 20 + kb + tg]);
                af[mi][1] = __float_as_uint(sA[(r + 8) * 20 + kb + tg]);
                af[mi][2] = __float_as_uint(sA[r * 20 + kb + tg + 4]);
                af[mi][3] = __float_as_uint(sA[(r + 8) * 20 + kb + tg + 4]);
            }
#pragma unroll
            for (int ni = 0; ni < 4; ni++) {
                int c = wn * 32 + ni * 8 + g;
                bf[ni][0] = __float_as_uint(sB[c * 20 + kb + tg]);
                bf[ni][1] = __float_as_uint(sB[c * 20 + kb + tg + 4]);
            }
#pragma unroll
            for (int mi = 0; mi < 4; mi++)
#pragma unroll
                for (int ni = 0; ni < 4; ni++)
                    mma_tf32(acc[mi][ni], af[mi], bf[ni]);
        }
    }

    if (MODE == 0) {
        const int sel = bn >> 11;
        const int h   = (bn & 2047) >> 7;
        float* dst = (sel == 0) ? g_q : (sel == 1) ? g_k : g_v;
        const float sc = (sel == 0) ? SCALE : 1.f;
#pragma unroll
        for (int mi = 0; mi < 4; mi++)
#pragma unroll
            for (int ni = 0; ni < 4; ni++) {
                const int d0 = wn * 32 + ni * 8 + tg * 2;
#pragma unroll
                for (int hr = 0; hr < 2; hr++) {
                    int m = bm + wm * 64 + mi * 16 + g + hr * 8;
                    int b = m >> 11, t = m & 2047;
                    float e = acc[mi][ni][hr * 2 + 0];
                    float o = acc[mi][ni][hr * 2 + 1];
                    if (sel < 2) {
                        int i0 = d0 >> 1;
                        float c = cosb[t * 64 + i0], s = sinb[t * 64 + i0];
                        float re = (e * c - o * s) * sc;
                        float ro = (e * s + o * c) * sc;
                        e = re; o = ro;
                    }
                    *(float2*)&dst[((size_t)(b * NHH + h) * TT + t) * HDD + d0] =
                        make_float2(rtf(e), rtf(o));
                }
            }
    } else {
#pragma unroll
        for (int mi = 0; mi < 4; mi++)
#pragma unroll
            for (int ni = 0; ni < 4; ni++) {
                const int n = bn + wn * 32 + ni * 8 + tg * 2;
                const float2 bi = *(const float2*)&bias[n];
#pragma unroll
                for (int hr = 0; hr < 2; hr++) {
                    int m = bm + wm * 64 + mi * 16 + g + hr * 8;
                    *(float2*)&Cout[(size_t)m * HIDD + n] =
                        make_float2(acc[mi][ni][hr * 2 + 0] + bi.x,
                                    acc[mi][ni][hr * 2 + 1] + bi.y);
                }
            }
    }
}

// ---------------- Flash attention: 128 q/block, 8 warps x 16 rows ----------------
#define AKW (64*132)
#define AVW (64*136)
#define APO (2*AKW + 2*AVW)
#define ATTN_WORDS (APO + 8*16*68)
#define ATTN_SMEM (ATTN_WORDS * 4)

__global__ __launch_bounds__(256, 1)
void attn_kernel()
{
    extern __shared__ float sm[];
    float* K0 = sm;           float* K1 = sm + AKW;
    float* V0 = sm + 2*AKW;   float* V1 = sm + 2*AKW + AVW;

    const int tid = threadIdx.x;
    const int w = tid >> 5, lane = tid & 31;
    const int g = lane >> 2, tg = lane & 3;
    const int bh = blockIdx.y;
    const size_t base = (size_t)bh * TT * HDD;
    const int q0 = blockIdx.x << 7;

    uint32_t* Pp = (uint32_t*)(sm + APO) + w * (16 * 68);

    // Q fragments in registers (rows q0+16w+g, +8)
    uint32_t qf[16][4];
    {
        const float* Qp = g_q + base + (size_t)(q0 + w * 16) * HDD;
#pragma unroll
        for (int ka = 0; ka < 16; ka++) {
            qf[ka][0] = __float_as_uint(Qp[g * HDD + ka * 8 + tg]);
            qf[ka][1] = __float_as_uint(Qp[(g + 8) * HDD + ka * 8 + tg]);
            qf[ka][2] = __float_as_uint(Qp[g * HDD + ka * 8 + tg + 4]);
            qf[ka][3] = __float_as_uint(Qp[(g + 8) * HDD + ka * 8 + tg + 4]);
        }
    }

    float oacc[16][4];
#pragma unroll
    for (int n = 0; n < 16; n++)
#pragma unroll
        for (int j = 0; j < 4; j++) oacc[n][j] = 0.f;
    float m0 = -1e30f, m1 = -1e30f, l0 = 0.f, l1 = 0.f;

    {   // stage tile 0 (64 rows x 32 float4 = 2048 cp16s each for K and V)
        const float* Kg = g_k + base;
        const float* Vg = g_v + base;
#pragma unroll
        for (int u = 0; u < 8; u++) {
            int id = tid + u * 256;
            int r = id >> 5, cw = (id & 31) << 2;
            cp16(&K0[r * 132 + cw], Kg + (size_t)r * HDD + cw);
            cp16(&V0[r * 136 + cw], Vg + (size_t)r * HDD + cw);
        }
        CPC;
    }

#pragma unroll 1
    for (int kt = 0; kt < TT / 64; kt++) {
        CPW(0);
        __syncthreads();
        if (kt + 1 < TT / 64) {
            const int k0n = (kt + 1) << 6;
            float* Kd = ((kt + 1) & 1) ? K1 : K0;
            float* Vd = ((kt + 1) & 1) ? V1 : V0;
            const float* Kg = g_k + base + (size_t)k0n * HDD;
            const float* Vg = g_v + base + (size_t)k0n * HDD;
#pragma unroll
            for (int u = 0; u < 8; u++) {
                int id = tid + u * 256;
                int r = id >> 5, cw = (id & 31) << 2;
                cp16(&Kd[r * 132 + cw], Kg + (size_t)r * HDD + cw);
                cp16(&Vd[r * 136 + cw], Vg + (size_t)r * HDD + cw);
            }
            CPC;
        }
        const float* K = (kt & 1) ? K1 : K0;
        const float* V = (kt & 1) ? V1 : V0;

        // S = Q*K^T (16x64 per warp)
        float sacc[8][4];
#pragma unroll
        for (int n = 0; n < 8; n++)
#pragma unroll
            for (int j = 0; j < 4; j++) sacc[n][j] = 0.f;
        const float* Kg2 = K + g * 132;
#pragma unroll
        for (int ka = 0; ka < 16; ka++) {
            const int c0 = ka * 8 + tg;
#pragma unroll
            for (int n = 0; n < 8; n++) {
                uint32_t b[2];
                b[0] = __float_as_uint(Kg2[n * 1056 + c0]);
                b[1] = __float_as_uint(Kg2[n * 1056 + c0 + 4]);
                mma_tf32(sacc[n], qf[ka], b);
            }
        }

        // online softmax in registers (quad = row)
        float mx0 = -1e30f, mx1 = -1e30f;
#pragma unroll
        for (int n = 0; n < 8; n++) {
            mx0 = fmaxf(mx0, fmaxf(sacc[n][0], sacc[n][1]));
            mx1 = fmaxf(mx1, fmaxf(sacc[n][2], sacc[n][3]));
        }
        mx0 = fmaxf(mx0, __shfl_xor_sync(0xffffffffu, mx0, 1));
        mx0 = fmaxf(mx0, __shfl_xor_sync(0xffffffffu, mx0, 2));
        mx1 = fmaxf(mx1, __shfl_xor_sync(0xffffffffu, mx1, 1));
        mx1 = fmaxf(mx1, __shfl_xor_sync(0xffffffffu, mx1, 2));
        const float mn0 = fmaxf(m0, mx0), mn1 = fmaxf(m1, mx1);
        const float a0 = __expf(m0 - mn0), a1 = __expf(m1 - mn1);
        float s0 = 0.f, s1 = 0.f;
        uint32_t pf[8][4];
#pragma unroll
        for (int n = 0; n < 8; n++) {
            float p00 = __expf(sacc[n][0] - mn0);
            float p01 = __expf(sacc[n][1] - mn0);
            float p10 = __expf(sacc[n][2] - mn1);
            float p11 = __expf(sacc[n][3] - mn1);
            s0 += p00 + p01; s1 += p10 + p11;
            pf[n][0] = f2tf(p00); pf[n][1] = f2tf(p01);
            pf[n][2] = f2tf(p10); pf[n][3] = f2tf(p11);
        }
        s0 += __shfl_xor_sync(0xffffffffu, s0, 1);
        s0 += __shfl_xor_sync(0xffffffffu, s0, 2);
        s1 += __shfl_xor_sync(0xffffffffu, s1, 1);
        s1 += __shfl_xor_sync(0xffffffffu, s1, 2);
        l0 = l0 * a0 + s0; l1 = l1 * a1 + s1;
        m0 = mn0; m1 = mn1;
#pragma unroll
        for (int n = 0; n < 16; n++) {
            oacc[n][0] *= a0; oacc[n][1] *= a0;
            oacc[n][2] *= a1; oacc[n][3] *= a1;
        }

        // P -> per-warp smem
#pragma unroll
        for (int n = 0; n < 8; n++) {
            *(uint2*)&Pp[g * 68 + n * 8 + 2 * tg]       = make_uint2(pf[n][0], pf[n][1]);
            *(uint2*)&Pp[(g + 8) * 68 + n * 8 + 2 * tg] = make_uint2(pf[n][2], pf[n][3]);
        }
        __syncwarp();

        // O += P*V (16x128 per warp)
#pragma unroll
        for (int ka = 0; ka < 8; ka++) {
            uint32_t ap[4];
            ap[0] = Pp[g * 68 + ka * 8 + tg];
            ap[1] = Pp[(g + 8) * 68 + ka * 8 + tg];
            ap[2] = Pp[g * 68 + ka * 8 + tg + 4];
            ap[3] = Pp[(g + 8) * 68 + ka * 8 + tg + 4];
            const int r0 = (ka * 8 + tg) * 136;
            const int r1 = (ka * 8 + tg + 4) * 136;
#pragma unroll
            for (int n = 0; n < 16; n++) {
                uint32_t b[2];
                b[0] = __float_as_uint(V[r0 + n * 8 + g]);
                b[1] = __float_as_uint(V[r1 + n * 8 + g]);
                mma_tf32(oacc[n], ap, b);
            }
        }
        __syncwarp();
    }

    // epilogue: normalize, round, write [b][t][hid]
    {
        const int b = bh >> 4, h = bh & 15;
        const int t0 = q0 + w * 16 + g, t1 = t0 + 8;
        const float i0 = 1.f / l0, i1 = 1.f / l1;
        float* O0 = g_attn + (size_t)(b * TT + t0) * HIDD + h * HDD;
        float* O1 = g_attn + (size_t)(b * TT + t1) * HIDD + h * HDD;
#pragma unroll
        for (int n = 0; n < 16; n++) {
            int d = n * 8 + tg * 2;
            *(float2*)&O0[d] = make_float2(rtf(oacc[n][0] * i0), rtf(oacc[n][1] * i0));
            *(float2*)&O1[d] = make_float2(rtf(oacc[n][2] * i1), rtf(oacc[n][3] * i1));
        }
    }
}

// ---------------------------------------------------------------------------
extern "C" void kernel_launch(void* const* d_in, const int* in_sizes, int n_in,
                              void* d_out, int out_size)
{
    (void)in_sizes; (void)n_in; (void)out_size;
    const float* x      = (const float*)d_in[0];
    const float* w_qkv  = (const float*)d_in[1];
    const float* w_proj = (const float*)d_in[2];
    const float* b_proj = (const float*)d_in[3];
    const float* cosb   = (const float*)d_in[4];
    const float* sinb   = (const float*)d_in[5];
    float* out = (float*)d_out;

    cudaFuncSetAttribute(attn_kernel,
        cudaFuncAttributeMaxDynamicSharedMemorySize, ATTN_SMEM);
    cudaFuncSetAttribute(gemm_tf32<0>,
        cudaFuncAttributeMaxDynamicSharedMemorySize, GEMM_SMEM);
    cudaFuncSetAttribute(gemm_tf32<1>,
        cudaFuncAttributeMaxDynamicSharedMemorySize, GEMM_SMEM);

    float *gx, *gw1, *gw2;
    cudaGetSymbolAddress((void**)&gx,  g_x);
    cudaGetSymbolAddress((void**)&gw1, g_w1);
    cudaGetSymbolAddress((void**)&gw2, g_w2);

    round_k<<<NX  / 1024, 256>>>(x,      gx);
    round_k<<<NW1 / 1024, 256>>>(w_qkv,  gw1);
    round_k<<<NW2 / 1024, 256>>>(w_proj, gw2);

    dim3 blk(256);
    dim3 g0(NQKV / 128, MTOT / 128);
    gemm_tf32<0><<<g0, blk, GEMM_SMEM>>>(cosb, sinb, nullptr, nullptr);

    dim3 ga(TT / 128, BB * NHH);
    attn_kernel<<<ga, blk, ATTN_SMEM>>>();

    dim3 g1(HIDD / 128, MTOT / 128);
    gemm_tf32<1><<<g1, blk, GEMM_SMEM>>>(nullptr, nullptr, b_proj, out);
}

// round 8
// speedup vs baseline: 4.9397x; 1.1340x over previous
#include <cuda_runtime.h>
#include <math.h>
#include <stdint.h>

#define BB   4
#define TT   2048
#define HIDD 2048
#define NHH  16
#define HDD  128
#define MTOT (BB*TT)
#define NQKV (3*HIDD)
#define NX   (MTOT*HIDD)
#define NW1  (NQKV*HIDD)
#define NW2  (HIDD*HIDD)
#define SCALE 0.08838834764831845f

__device__ float g_q[BB*NHH*TT*HDD];
__device__ float g_k[BB*NHH*TT*HDD];
__device__ float g_v[BB*NHH*TT*HDD];
__device__ float g_attn[BB*TT*HIDD];
__device__ float g_x[NX];
__device__ float g_w1[NW1];
__device__ float g_w2[NW2];

__device__ __forceinline__ uint32_t f2tf(float f) {
    uint32_t u; asm("cvt.rna.tf32.f32 %0, %1;" : "=r"(u) : "f"(f)); return u;
}
__device__ __forceinline__ float rtf(float f) { return __uint_as_float(f2tf(f)); }

__device__ __forceinline__ void mma_tf32(float* c, const uint32_t* a, const uint32_t* b) {
    asm volatile(
        "mma.sync.aligned.m16n8k8.row.col.f32.tf32.tf32.f32 "
        "{%0,%1,%2,%3}, {%4,%5,%6,%7}, {%8,%9}, {%0,%1,%2,%3};\n"
        : "+f"(c[0]), "+f"(c[1]), "+f"(c[2]), "+f"(c[3])
        : "r"(a[0]), "r"(a[1]), "r"(a[2]), "r"(a[3]), "r"(b[0]), "r"(b[1]));
}
__device__ __forceinline__ void cp16(void* s, const void* g) {
    uint32_t sa = (uint32_t)__cvta_generic_to_shared(s);
    asm volatile("cp.async.cg.shared.global [%0], [%1], 16;" :: "r"(sa), "l"(g));
}
#define CPC    asm volatile("cp.async.commit_group;")
#define CPW(n) asm volatile("cp.async.wait_group %0;" :: "n"(n))

// ldmatrix x4 on 32-bit (tf32) data: 8x4-tf32 submatrix == 8x8 b16 matrix;
// thread t receives element [t/4][t%4] = the tf32 fragment ownership map.
__device__ __forceinline__ void ldsm4(uint32_t& r0, uint32_t& r1,
                                      uint32_t& r2, uint32_t& r3, uint32_t a) {
    asm volatile("ldmatrix.sync.aligned.m8n8.x4.shared.b16 {%0,%1,%2,%3}, [%4];"
        : "=r"(r0), "=r"(r1), "=r"(r2), "=r"(r3) : "r"(a));
}

// ---------------- pre-round inputs to tf32 ----------------
__global__ void round_k(const float* __restrict__ in, float* __restrict__ outp) {
    int i = (blockIdx.x * 256 + threadIdx.x) * 4;
    float4 v = *(const float4*)(in + i);
    *(float4*)(outp + i) = make_float4(rtf(v.x), rtf(v.y), rtf(v.z), rtf(v.w));
}

// ---------------- tf32 GEMM, 3-stage cp.async, ldmatrix frags ----------------
#define GAW (128*20)
#define GEMM_SMEM (3 * 2 * GAW * 4)

template<int MODE>
__global__ __launch_bounds__(256, 2)
void gemm_tf32(const float* __restrict__ cosb, const float* __restrict__ sinb,
               const float* __restrict__ bias, float* __restrict__ Cout)
{
    extern __shared__ float gs[];
    const int tid  = threadIdx.x;
    const int w    = tid >> 5, lane = tid & 31;
    const int g    = lane >> 2, tg = lane & 3;
    const int wm   = w >> 2, wn = w & 3;
    const int bm   = blockIdx.y << 7, bn = blockIdx.x << 7;
    const int lr = tid >> 2, lc = (tid & 3) << 2;

    // ldsm lane address components
    // A mats: (rows r..r+7 | r+8..r+15) x (k kb | kb+4)
    const int rowA = wm * 64 + (lane & 7) + ((lane >> 3) & 1) * 8;
    const int colA = (lane >> 4) * 4;
    // B mats: (rows c..c+7, k kb | kb+4) then (rows c+8..c+15, ...)
    const int rowB = wn * 32 + (lane & 7) + (lane >> 4) * 8;
    const int colB = ((lane >> 3) & 1) * 4;

    const float* Ap = ((MODE == 0) ? g_x  : g_attn) + (size_t)(bm + lr) * HIDD + lc;
    const float* Bp = ((MODE == 0) ? g_w1 : g_w2)   + (size_t)(bn + lr) * HIDD + lc;

    float acc[4][4][4];
#pragma unroll
    for (int i = 0; i < 4; i++)
#pragma unroll
        for (int j = 0; j < 4; j++)
#pragma unroll
            for (int q = 0; q < 4; q++) acc[i][j][q] = 0.f;

#pragma unroll
    for (int c = 0; c < 2; c++) {
        float* sA = gs + c * 2 * GAW; float* sB = sA + GAW;
        cp16(&sA[lr * 20 + lc],        Ap + c * 16);
        cp16(&sA[(lr + 64) * 20 + lc], Ap + 64 * HIDD + c * 16);
        cp16(&sB[lr * 20 + lc],        Bp + c * 16);
        cp16(&sB[(lr + 64) * 20 + lc], Bp + 64 * HIDD + c * 16);
        CPC;
    }

#pragma unroll 1
    for (int kc = 0; kc < HIDD / 16; kc++) {
        CPW(1);
        __syncthreads();
        if (kc + 2 < HIDD / 16) {
            int c = kc + 2;
            float* sA = gs + (c % 3) * 2 * GAW; float* sB = sA + GAW;
            cp16(&sA[lr * 20 + lc],        Ap + c * 16);
            cp16(&sA[(lr + 64) * 20 + lc], Ap + 64 * HIDD + c * 16);
            cp16(&sB[lr * 20 + lc],        Bp + c * 16);
            cp16(&sB[(lr + 64) * 20 + lc], Bp + 64 * HIDD + c * 16);
        }
        CPC;

        float* sA = gs + (kc % 3) * 2 * GAW;
        float* sB = sA + GAW;
        const uint32_t sAu = (uint32_t)__cvta_generic_to_shared(sA);
        const uint32_t sBu = (uint32_t)__cvta_generic_to_shared(sB);
#pragma unroll
        for (int ka = 0; ka < 2; ka++) {
            const int kb = ka << 3;
            uint32_t af[4][4], bf[4][2];
#pragma unroll
            for (int mi = 0; mi < 4; mi++)
                ldsm4(af[mi][0], af[mi][1], af[mi][2], af[mi][3],
                      sAu + (uint32_t)(((rowA + mi * 16) * 20 + kb + colA) * 4));
#pragma unroll
            for (int p = 0; p < 2; p++)
                ldsm4(bf[2*p][0], bf[2*p][1], bf[2*p+1][0], bf[2*p+1][1],
                      sBu + (uint32_t)(((rowB + p * 16) * 20 + kb + colB) * 4));
#pragma unroll
            for (int mi = 0; mi < 4; mi++)
#pragma unroll
                for (int ni = 0; ni < 4; ni++)
                    mma_tf32(acc[mi][ni], af[mi], bf[ni]);
        }
    }

    if (MODE == 0) {
        const int sel = bn >> 11;
        const int h   = (bn & 2047) >> 7;
        float* dst = (sel == 0) ? g_q : (sel == 1) ? g_k : g_v;
        const float sc = (sel == 0) ? SCALE : 1.f;
#pragma unroll
        for (int mi = 0; mi < 4; mi++)
#pragma unroll
            for (int ni = 0; ni < 4; ni++) {
                const int d0 = wn * 32 + ni * 8 + tg * 2;
#pragma unroll
                for (int hr = 0; hr < 2; hr++) {
                    int m = bm + wm * 64 + mi * 16 + g + hr * 8;
                    int b = m >> 11, t = m & 2047;
                    float e = acc[mi][ni][hr * 2 + 0];
                    float o = acc[mi][ni][hr * 2 + 1];
                    if (sel < 2) {
                        int i0 = d0 >> 1;
                        float c = cosb[t * 64 + i0], s = sinb[t * 64 + i0];
                        float re = (e * c - o * s) * sc;
                        float ro = (e * s + o * c) * sc;
                        e = re; o = ro;
                    }
                    *(float2*)&dst[((size_t)(b * NHH + h) * TT + t) * HDD + d0] =
                        make_float2(rtf(e), rtf(o));
                }
            }
    } else {
#pragma unroll
        for (int mi = 0; mi < 4; mi++)
#pragma unroll
            for (int ni = 0; ni < 4; ni++) {
                const int n = bn + wn * 32 + ni * 8 + tg * 2;
                const float2 bi = *(const float2*)&bias[n];
#pragma unroll
                for (int hr = 0; hr < 2; hr++) {
                    int m = bm + wm * 64 + mi * 16 + g + hr * 8;
                    *(float2*)&Cout[(size_t)m * HIDD + n] =
                        make_float2(acc[mi][ni][hr * 2 + 0] + bi.x,
                                    acc[mi][ni][hr * 2 + 1] + bi.y);
                }
            }
    }
}

// ---------------- Flash attention: 128 q/block, 8 warps x 16 rows ----------------
#define AKW (64*132)
#define AVW (64*136)
#define APO (2*AKW + 2*AVW)
#define ATTN_WORDS (APO + 8*16*68)
#define ATTN_SMEM (ATTN_WORDS * 4)

__global__ __launch_bounds__(256, 1)
void attn_kernel()
{
    extern __shared__ float sm[];
    float* K0 = sm;           float* K1 = sm + AKW;
    float* V0 = sm + 2*AKW;   float* V1 = sm + 2*AKW + AVW;

    const int tid = threadIdx.x;
    const int w = tid >> 5, lane = tid & 31;
    const int g = lane >> 2, tg = lane & 3;
    const int bh = blockIdx.y;
    const size_t base = (size_t)bh * TT * HDD;
    const int q0 = blockIdx.x << 7;

    uint32_t* Pp = (uint32_t*)(sm + APO) + w * (16 * 68);
    const uint32_t Pu = (uint32_t)__cvta_generic_to_shared(Pp);

    // ldsm lane address components
    const int rowBa = (lane & 7) + (lane >> 4) * 8;        // K (B-operand) rows
    const int colBa = ((lane >> 3) & 1) * 4;
    const int rowAa = (lane & 7) + ((lane >> 3) & 1) * 8;  // P (A-operand) rows
    const int colAa = (lane >> 4) * 4;

    // Q fragments in registers (rows q0+16w+g, +8)
    uint32_t qf[16][4];
    {
        const float* Qp = g_q + base + (size_t)(q0 + w * 16) * HDD;
#pragma unroll
        for (int ka = 0; ka < 16; ka++) {
            qf[ka][0] = __float_as_uint(Qp[g * HDD + ka * 8 + tg]);
            qf[ka][1] = __float_as_uint(Qp[(g + 8) * HDD + ka * 8 + tg]);
            qf[ka][2] = __float_as_uint(Qp[g * HDD + ka * 8 + tg + 4]);
            qf[ka][3] = __float_as_uint(Qp[(g + 8) * HDD + ka * 8 + tg + 4]);
        }
    }

    float oacc[16][4];
#pragma unroll
    for (int n = 0; n < 16; n++)
#pragma unroll
        for (int j = 0; j < 4; j++) oacc[n][j] = 0.f;
    float m0 = -1e30f, m1 = -1e30f, l0 = 0.f, l1 = 0.f;

    {   // stage tile 0
        const float* Kg = g_k + base;
        const float* Vg = g_v + base;
#pragma unroll
        for (int u = 0; u < 8; u++) {
            int id = tid + u * 256;
            int r = id >> 5, cw = (id & 31) << 2;
            cp16(&K0[r * 132 + cw], Kg + (size_t)r * HDD + cw);
            cp16(&V0[r * 136 + cw], Vg + (size_t)r * HDD + cw);
        }
        CPC;
    }

#pragma unroll 1
    for (int kt = 0; kt < TT / 64; kt++) {
        CPW(0);
        __syncthreads();
        if (kt + 1 < TT / 64) {
            const int k0n = (kt + 1) << 6;
            float* Kd = ((kt + 1) & 1) ? K1 : K0;
            float* Vd = ((kt + 1) & 1) ? V1 : V0;
            const float* Kg = g_k + base + (size_t)k0n * HDD;
            const float* Vg = g_v + base + (size_t)k0n * HDD;
#pragma unroll
            for (int u = 0; u < 8; u++) {
                int id = tid + u * 256;
                int r = id >> 5, cw = (id & 31) << 2;
                cp16(&Kd[r * 132 + cw], Kg + (size_t)r * HDD + cw);
                cp16(&Vd[r * 136 + cw], Vg + (size_t)r * HDD + cw);
            }
            CPC;
        }
        const float* K = (kt & 1) ? K1 : K0;
        const float* V = (kt & 1) ? V1 : V0;
        const uint32_t Ku = (uint32_t)__cvta_generic_to_shared(K);

        // S = Q*K^T (16x64 per warp), K frags via ldmatrix
        float sacc[8][4];
#pragma unroll
        for (int n = 0; n < 8; n++)
#pragma unroll
            for (int j = 0; j < 4; j++) sacc[n][j] = 0.f;
#pragma unroll
        for (int ka = 0; ka < 16; ka++) {
            const int kb = ka << 3;
            uint32_t bk[8][2];
#pragma unroll
            for (int p = 0; p < 4; p++)
                ldsm4(bk[2*p][0], bk[2*p][1], bk[2*p+1][0], bk[2*p+1][1],
                      Ku + (uint32_t)(((p * 16 + rowBa) * 132 + kb + colBa) * 4));
#pragma unroll
            for (int n = 0; n < 8; n++)
                mma_tf32(sacc[n], qf[ka], bk[n]);
        }

        // online softmax in registers (quad = row)
        float mx0 = -1e30f, mx1 = -1e30f;
#pragma unroll
        for (int n = 0; n < 8; n++) {
            mx0 = fmaxf(mx0, fmaxf(sacc[n][0], sacc[n][1]));
            mx1 = fmaxf(mx1, fmaxf(sacc[n][2], sacc[n][3]));
        }
        mx0 = fmaxf(mx0, __shfl_xor_sync(0xffffffffu, mx0, 1));
        mx0 = fmaxf(mx0, __shfl_xor_sync(0xffffffffu, mx0, 2));
        mx1 = fmaxf(mx1, __shfl_xor_sync(0xffffffffu, mx1, 1));
        mx1 = fmaxf(mx1, __shfl_xor_sync(0xffffffffu, mx1, 2));
        const float mn0 = fmaxf(m0, mx0), mn1 = fmaxf(m1, mx1);
        const float a0 = __expf(m0 - mn0), a1 = __expf(m1 - mn1);
        float s0 = 0.f, s1 = 0.f;
        uint32_t pf[8][4];
#pragma unroll
        for (int n = 0; n < 8; n++) {
            float p00 = __expf(sacc[n][0] - mn0);
            float p01 = __expf(sacc[n][1] - mn0);
            float p10 = __expf(sacc[n][2] - mn1);
            float p11 = __expf(sacc[n][3] - mn1);
            s0 += p00 + p01; s1 += p10 + p11;
            pf[n][0] = f2tf(p00); pf[n][1] = f2tf(p01);
            pf[n][2] = f2tf(p10); pf[n][3] = f2tf(p11);
        }
        s0 += __shfl_xor_sync(0xffffffffu, s0, 1);
        s0 += __shfl_xor_sync(0xffffffffu, s0, 2);
        s1 += __shfl_xor_sync(0xffffffffu, s1, 1);
        s1 += __shfl_xor_sync(0xffffffffu, s1, 2);
        l0 = l0 * a0 + s0; l1 = l1 * a1 + s1;
        m0 = mn0; m1 = mn1;
#pragma unroll
        for (int n = 0; n < 16; n++) {
            oacc[n][0] *= a0; oacc[n][1] *= a0;
            oacc[n][2] *= a1; oacc[n][3] *= a1;
        }

        // P -> per-warp smem
#pragma unroll
        for (int n = 0; n < 8; n++) {
            *(uint2*)&Pp[g * 68 + n * 8 + 2 * tg]       = make_uint2(pf[n][0], pf[n][1]);
            *(uint2*)&Pp[(g + 8) * 68 + n * 8 + 2 * tg] = make_uint2(pf[n][2], pf[n][3]);
        }
        __syncwarp();

        // O += P*V (16x128 per warp), P frags via ldmatrix
#pragma unroll
        for (int ka = 0; ka < 8; ka++) {
            uint32_t ap[4];
            ldsm4(ap[0], ap[1], ap[2], ap[3],
                  Pu + (uint32_t)((rowAa * 68 + ka * 8 + colAa) * 4));
            const int r0 = (ka * 8 + tg) * 136;
            const int r1 = (ka * 8 + tg + 4) * 136;
#pragma unroll
            for (int n = 0; n < 16; n++) {
                uint32_t b[2];
                b[0] = __float_as_uint(V[r0 + n * 8 + g]);
                b[1] = __float_as_uint(V[r1 + n * 8 + g]);
                mma_tf32(oacc[n], ap, b);
            }
        }
        __syncwarp();
    }

    // epilogue: normalize, round, write [b][t][hid]
    {
        const int b = bh >> 4, h = bh & 15;
        const int t0 = q0 + w * 16 + g, t1 = t0 + 8;
        const float i0 = 1.f / l0, i1 = 1.f / l1;
        float* O0 = g_attn + (size_t)(b * TT + t0) * HIDD + h * HDD;
        float* O1 = g_attn + (size_t)(b * TT + t1) * HIDD + h * HDD;
#pragma unroll
        for (int n = 0; n < 16; n++) {
            int d = n * 8 + tg * 2;
            *(float2*)&O0[d] = make_float2(rtf(oacc[n][0] * i0), rtf(oacc[n][1] * i0));
            *(float2*)&O1[d] = make_float2(rtf(oacc[n][2] * i1), rtf(oacc[n][3] * i1));
        }
    }
}

// ---------------------------------------------------------------------------
extern "C" void kernel_launch(void* const* d_in, const int* in_sizes, int n_in,
                              void* d_out, int out_size)
{
    (void)in_sizes; (void)n_in; (void)out_size;
    const float* x      = (const float*)d_in[0];
    const float* w_qkv  = (const float*)d_in[1];
    const float* w_proj = (const float*)d_in[2];
    const float* b_proj = (const float*)d_in[3];
    const float* cosb   = (const float*)d_in[4];
    const float* sinb   = (const float*)d_in[5];
    float* out = (float*)d_out;

    cudaFuncSetAttribute(attn_kernel,
        cudaFuncAttributeMaxDynamicSharedMemorySize, ATTN_SMEM);
    cudaFuncSetAttribute(gemm_tf32<0>,
        cudaFuncAttributeMaxDynamicSharedMemorySize, GEMM_SMEM);
    cudaFuncSetAttribute(gemm_tf32<1>,
        cudaFuncAttributeMaxDynamicSharedMemorySize, GEMM_SMEM);

    float *gx, *gw1, *gw2;
    cudaGetSymbolAddress((void**)&gx,  g_x);
    cudaGetSymbolAddress((void**)&gw1, g_w1);
    cudaGetSymbolAddress((void**)&gw2, g_w2);

    round_k<<<NX  / 1024, 256>>>(x,      gx);
    round_k<<<NW1 / 1024, 256>>>(w_qkv,  gw1);
    round_k<<<NW2 / 1024, 256>>>(w_proj, gw2);

    dim3 blk(256);
    dim3 g0(NQKV / 128, MTOT / 128);
    gemm_tf32<0><<<g0, blk, GEMM_SMEM>>>(cosb, sinb, nullptr, nullptr);

    dim3 ga(TT / 128, BB * NHH);
    attn_kernel<<<ga, blk, ATTN_SMEM>>>();

    dim3 g1(HIDD / 128, MTOT / 128);
    gemm_tf32<1><<<g1, blk, GEMM_SMEM>>>(nullptr, nullptr, b_proj, out);
}

// round 9
// speedup vs baseline: 5.1896x; 1.0506x over previous
#include <cuda_runtime.h>
#include <math.h>
#include <stdint.h>

#define BB   4
#define TT   2048
#define HIDD 2048
#define NHH  16
#define HDD  128
#define MTOT (BB*TT)
#define NQKV (3*HIDD)
#define NX   (MTOT*HIDD)
#define NW1  (NQKV*HIDD)
#define NW2  (HIDD*HIDD)
#define SCALE 0.08838834764831845f

__device__ float g_q[BB*NHH*TT*HDD];
__device__ float g_k[BB*NHH*TT*HDD];
__device__ float g_v[BB*NHH*TT*HDD];
__device__ float g_attn[BB*TT*HIDD];
__device__ float g_x[NX];
__device__ float g_w1[NW1];
__device__ float g_w2[NW2];

__device__ __forceinline__ uint32_t f2tf(float f) {
    uint32_t u; asm("cvt.rna.tf32.f32 %0, %1;" : "=r"(u) : "f"(f)); return u;
}
__device__ __forceinline__ float rtf(float f) { return __uint_as_float(f2tf(f)); }

__device__ __forceinline__ void mma_tf32(float* c, const uint32_t* a, const uint32_t* b) {
    asm volatile(
        "mma.sync.aligned.m16n8k8.row.col.f32.tf32.tf32.f32 "
        "{%0,%1,%2,%3}, {%4,%5,%6,%7}, {%8,%9}, {%0,%1,%2,%3};\n"
        : "+f"(c[0]), "+f"(c[1]), "+f"(c[2]), "+f"(c[3])
        : "r"(a[0]), "r"(a[1]), "r"(a[2]), "r"(a[3]), "r"(b[0]), "r"(b[1]));
}
__device__ __forceinline__ void cp16(void* s, const void* g) {
    uint32_t sa = (uint32_t)__cvta_generic_to_shared(s);
    asm volatile("cp.async.cg.shared.global [%0], [%1], 16;" :: "r"(sa), "l"(g));
}
#define CPC    asm volatile("cp.async.commit_group;")
#define CPW(n) asm volatile("cp.async.wait_group %0;" :: "n"(n))

__device__ __forceinline__ void ldsm4(uint32_t& r0, uint32_t& r1,
                                      uint32_t& r2, uint32_t& r3, uint32_t a) {
    asm volatile("ldmatrix.sync.aligned.m8n8.x4.shared.b16 {%0,%1,%2,%3}, [%4];"
        : "=r"(r0), "=r"(r1), "=r"(r2), "=r"(r3) : "r"(a));
}

// ---------------- pre-round inputs to tf32 ----------------
__global__ void round_k(const float* __restrict__ in, float* __restrict__ outp) {
    int i = (blockIdx.x * 256 + threadIdx.x) * 4;
    float4 v = *(const float4*)(in + i);
    *(float4*)(outp + i) = make_float4(rtf(v.x), rtf(v.y), rtf(v.z), rtf(v.w));
}

// ---------------- tf32 GEMM, 3-stage cp.async, k-chunk 32 ----------------
#define GST 36               // stride: banks 4r mod 32 -> conflict-free ldsm
#define GAW (128*GST)
#define GEMM_SMEM (3 * 2 * GAW * 4)   // 110592 B -> 2 CTAs/SM

template<int MODE>
__global__ __launch_bounds__(256, 2)
void gemm_tf32(const float* __restrict__ cosb, const float* __restrict__ sinb,
               const float* __restrict__ bias, float* __restrict__ Cout)
{
    extern __shared__ float gs[];
    const int tid  = threadIdx.x;
    const int w    = tid >> 5, lane = tid & 31;
    const int g    = lane >> 2, tg = lane & 3;
    const int wm   = w >> 2, wn = w & 3;
    const int bm   = blockIdx.y << 7, bn = blockIdx.x << 7;
    const int r2 = tid >> 3;            // 0..31
    const int c2 = (tid & 7) << 2;      // 0,4,..,28

    const int rowA = wm * 64 + (lane & 7) + ((lane >> 3) & 1) * 8;
    const int colA = (lane >> 4) * 4;
    const int rowB = wn * 32 + (lane & 7) + (lane >> 4) * 8;
    const int colB = ((lane >> 3) & 1) * 4;

    const float* Ap = ((MODE == 0) ? g_x  : g_attn) + (size_t)(bm + r2) * HIDD + c2;
    const float* Bp = ((MODE == 0) ? g_w1 : g_w2)   + (size_t)(bn + r2) * HIDD + c2;

    float acc[4][4][4];
#pragma unroll
    for (int i = 0; i < 4; i++)
#pragma unroll
        for (int j = 0; j < 4; j++)
#pragma unroll
            for (int q = 0; q < 4; q++) acc[i][j][q] = 0.f;

#pragma unroll
    for (int c = 0; c < 2; c++) {
        float* sA = gs + c * 2 * GAW; float* sB = sA + GAW;
#pragma unroll
        for (int p = 0; p < 4; p++) {
            cp16(&sA[(r2 + p * 32) * GST + c2], Ap + (size_t)(p * 32) * HIDD + c * 32);
            cp16(&sB[(r2 + p * 32) * GST + c2], Bp + (size_t)(p * 32) * HIDD + c * 32);
        }
        CPC;
    }

#pragma unroll 1
    for (int kc = 0; kc < HIDD / 32; kc++) {
        CPW(1);
        __syncthreads();
        if (kc + 2 < HIDD / 32) {
            int c = kc + 2;
            float* sA = gs + (c % 3) * 2 * GAW; float* sB = sA + GAW;
#pragma unroll
            for (int p = 0; p < 4; p++) {
                cp16(&sA[(r2 + p * 32) * GST + c2], Ap + (size_t)(p * 32) * HIDD + c * 32);
                cp16(&sB[(r2 + p * 32) * GST + c2], Bp + (size_t)(p * 32) * HIDD + c * 32);
            }
        }
        CPC;

        float* sA = gs + (kc % 3) * 2 * GAW;
        float* sB = sA + GAW;
        const uint32_t sAu = (uint32_t)__cvta_generic_to_shared(sA);
        const uint32_t sBu = (uint32_t)__cvta_generic_to_shared(sB);
#pragma unroll
        for (int ka = 0; ka < 4; ka++) {
            const int kb = ka << 3;
            uint32_t af[4][4], bf[4][2];
#pragma unroll
            for (int mi = 0; mi < 4; mi++)
                ldsm4(af[mi][0], af[mi][1], af[mi][2], af[mi][3],
                      sAu + (uint32_t)(((rowA + mi * 16) * GST + kb + colA) * 4));
#pragma unroll
            for (int p = 0; p < 2; p++)
                ldsm4(bf[2*p][0], bf[2*p][1], bf[2*p+1][0], bf[2*p+1][1],
                      sBu + (uint32_t)(((rowB + p * 16) * GST + kb + colB) * 4));
#pragma unroll
            for (int mi = 0; mi < 4; mi++)
#pragma unroll
                for (int ni = 0; ni < 4; ni++)
                    mma_tf32(acc[mi][ni], af[mi], bf[ni]);
        }
    }

    if (MODE == 0) {
        const int sel = bn >> 11;
        const int h   = (bn & 2047) >> 7;
        float* dst = (sel == 0) ? g_q : (sel == 1) ? g_k : g_v;
        const float sc = (sel == 0) ? SCALE : 1.f;
#pragma unroll
        for (int mi = 0; mi < 4; mi++)
#pragma unroll
            for (int ni = 0; ni < 4; ni++) {
                const int d0 = wn * 32 + ni * 8 + tg * 2;
#pragma unroll
                for (int hr = 0; hr < 2; hr++) {
                    int m = bm + wm * 64 + mi * 16 + g + hr * 8;
                    int b = m >> 11, t = m & 2047;
                    float e = acc[mi][ni][hr * 2 + 0];
                    float o = acc[mi][ni][hr * 2 + 1];
                    if (sel < 2) {
                        int i0 = d0 >> 1;
                        float c = cosb[t * 64 + i0], s = sinb[t * 64 + i0];
                        float re = (e * c - o * s) * sc;
                        float ro = (e * s + o * c) * sc;
                        e = re; o = ro;
                    }
                    *(float2*)&dst[((size_t)(b * NHH + h) * TT + t) * HDD + d0] =
                        make_float2(rtf(e), rtf(o));
                }
            }
    } else {
#pragma unroll
        for (int mi = 0; mi < 4; mi++)
#pragma unroll
            for (int ni = 0; ni < 4; ni++) {
                const int n = bn + wn * 32 + ni * 8 + tg * 2;
                const float2 bi = *(const float2*)&bias[n];
#pragma unroll
                for (int hr = 0; hr < 2; hr++) {
                    int m = bm + wm * 64 + mi * 16 + g + hr * 8;
                    *(float2*)&Cout[(size_t)m * HIDD + n] =
                        make_float2(acc[mi][ni][hr * 2 + 0] + bi.x,
                                    acc[mi][ni][hr * 2 + 1] + bi.y);
                }
            }
    }
}

// ---------------- Flash attention: 128 q/block, K-permuted, P stays in regs ----
#define AKW (64*132)
#define AVW (64*136)
#define ATTN_WORDS (2*AKW + 2*AVW)
#define ATTN_SMEM (ATTN_WORDS * 4)

// slot p of each 8-row K group holds key sigma(p); store key j at slot pi(j):
__device__ __constant__ int c_kperm[8] = {0, 2, 4, 6, 1, 3, 5, 7};

__global__ __launch_bounds__(256, 1)
void attn_kernel()
{
    extern __shared__ float sm[];
    float* K0 = sm;           float* K1 = sm + AKW;
    float* V0 = sm + 2*AKW;   float* V1 = sm + 2*AKW + AVW;

    const int tid = threadIdx.x;
    const int w = tid >> 5, lane = tid & 31;
    const int g = lane >> 2, tg = lane & 3;
    const int bh = blockIdx.y;
    const size_t base = (size_t)bh * TT * HDD;
    const int q0 = blockIdx.x << 7;

    const int rowBa = (lane & 7) + (lane >> 4) * 8;   // K ldsm rows
    const int colBa = ((lane >> 3) & 1) * 4;

    // Q fragments in registers
    uint32_t qf[16][4];
    {
        const float* Qp = g_q + base + (size_t)(q0 + w * 16) * HDD;
#pragma unroll
        for (int ka = 0; ka < 16; ka++) {
            qf[ka][0] = __float_as_uint(Qp[g * HDD + ka * 8 + tg]);
            qf[ka][1] = __float_as_uint(Qp[(g + 8) * HDD + ka * 8 + tg]);
            qf[ka][2] = __float_as_uint(Qp[g * HDD + ka * 8 + tg + 4]);
            qf[ka][3] = __float_as_uint(Qp[(g + 8) * HDD + ka * 8 + tg + 4]);
        }
    }

    float oacc[16][4];
#pragma unroll
    for (int n = 0; n < 16; n++)
#pragma unroll
        for (int j = 0; j < 4; j++) oacc[n][j] = 0.f;
    float m0 = -1e30f, m1 = -1e30f, l0 = 0.f, l1 = 0.f;

    {   // stage tile 0 (K rows permuted within 8-row groups)
        const float* Kg = g_k + base;
        const float* Vg = g_v + base;
#pragma unroll
        for (int u = 0; u < 8; u++) {
            int id = tid + u * 256;
            int r = id >> 5, cw = (id & 31) << 2;
            int rp = (r & ~7) | c_kperm[r & 7];
            cp16(&K0[rp * 132 + cw], Kg + (size_t)r * HDD + cw);
            cp16(&V0[r * 136 + cw],  Vg + (size_t)r * HDD + cw);
        }
        CPC;
    }

#pragma unroll 1
    for (int kt = 0; kt < TT / 64; kt++) {
        CPW(0);
        __syncthreads();
        if (kt + 1 < TT / 64) {
            const int k0n = (kt + 1) << 6;
            float* Kd = ((kt + 1) & 1) ? K1 : K0;
            float* Vd = ((kt + 1) & 1) ? V1 : V0;
            const float* Kg = g_k + base + (size_t)k0n * HDD;
            const float* Vg = g_v + base + (size_t)k0n * HDD;
#pragma unroll
            for (int u = 0; u < 8; u++) {
                int id = tid + u * 256;
                int r = id >> 5, cw = (id & 31) << 2;
                int rp = (r & ~7) | c_kperm[r & 7];
                cp16(&Kd[rp * 132 + cw], Kg + (size_t)r * HDD + cw);
                cp16(&Vd[r * 136 + cw],  Vg + (size_t)r * HDD + cw);
            }
            CPC;
        }
        const float* K = (kt & 1) ? K1 : K0;
        const float* V = (kt & 1) ? V1 : V0;
        const uint32_t Ku = (uint32_t)__cvta_generic_to_shared(K);

        // S = Q*K^T (16x64 per warp) on permuted K columns
        float sacc[8][4];
#pragma unroll
        for (int n = 0; n < 8; n++)
#pragma unroll
            for (int j = 0; j < 4; j++) sacc[n][j] = 0.f;
#pragma unroll
        for (int ka = 0; ka < 16; ka++) {
            const int kb = ka << 3;
            uint32_t bk[8][2];
#pragma unroll
            for (int p = 0; p < 4; p++)
                ldsm4(bk[2*p][0], bk[2*p][1], bk[2*p+1][0], bk[2*p+1][1],
                      Ku + (uint32_t)(((p * 16 + rowBa) * 132 + kb + colBa) * 4));
#pragma unroll
            for (int n = 0; n < 8; n++)
                mma_tf32(sacc[n], qf[ka], bk[n]);
        }

        // online softmax in registers (permutation-invariant per row)
        float mx0 = -1e30f, mx1 = -1e30f;
#pragma unroll
        for (int n = 0; n < 8; n++) {
            mx0 = fmaxf(mx0, fmaxf(sacc[n][0], sacc[n][1]));
            mx1 = fmaxf(mx1, fmaxf(sacc[n][2], sacc[n][3]));
        }
        mx0 = fmaxf(mx0, __shfl_xor_sync(0xffffffffu, mx0, 1));
        mx0 = fmaxf(mx0, __shfl_xor_sync(0xffffffffu, mx0, 2));
        mx1 = fmaxf(mx1, __shfl_xor_sync(0xffffffffu, mx1, 1));
        mx1 = fmaxf(mx1, __shfl_xor_sync(0xffffffffu, mx1, 2));
        const float mn0 = fmaxf(m0, mx0), mn1 = fmaxf(m1, mx1);
        const float a0 = __expf(m0 - mn0), a1 = __expf(m1 - mn1);
        float s0 = 0.f, s1 = 0.f;
        uint32_t pf[8][4];
#pragma unroll
        for (int n = 0; n < 8; n++) {
            float p00 = __expf(sacc[n][0] - mn0);
            float p01 = __expf(sacc[n][1] - mn0);
            float p10 = __expf(sacc[n][2] - mn1);
            float p11 = __expf(sacc[n][3] - mn1);
            s0 += p00 + p01; s1 += p10 + p11;
            // A-frag order: a0=c0 (g,tg), a1=c2 (g+8,tg), a2=c1 (g,tg+4), a3=c3
            pf[n][0] = f2tf(p00); pf[n][1] = f2tf(p10);
            pf[n][2] = f2tf(p01); pf[n][3] = f2tf(p11);
        }
        s0 += __shfl_xor_sync(0xffffffffu, s0, 1);
        s0 += __shfl_xor_sync(0xffffffffu, s0, 2);
        s1 += __shfl_xor_sync(0xffffffffu, s1, 1);
        s1 += __shfl_xor_sync(0xffffffffu, s1, 2);
        l0 = l0 * a0 + s0; l1 = l1 * a1 + s1;
        m0 = mn0; m1 = mn1;
#pragma unroll
        for (int n = 0; n < 16; n++) {
            oacc[n][0] *= a0; oacc[n][1] *= a0;
            oacc[n][2] *= a1; oacc[n][3] *= a1;
        }

        // O += P*V : P fragments direct from registers (no smem round-trip)
#pragma unroll
        for (int ka = 0; ka < 8; ka++) {
            const int r0 = (ka * 8 + tg) * 136;
            const int r1 = (ka * 8 + tg + 4) * 136;
#pragma unroll
            for (int n = 0; n < 16; n++) {
                uint32_t b[2];
                b[0] = __float_as_uint(V[r0 + n * 8 + g]);
                b[1] = __float_as_uint(V[r1 + n * 8 + g]);
                mma_tf32(oacc[n], pf[ka], b);
            }
        }
    }

    // epilogue: normalize, round, write [b][t][hid]
    {
        const int b = bh >> 4, h = bh & 15;
        const int t0 = q0 + w * 16 + g, t1 = t0 + 8;
        const float i0 = 1.f / l0, i1 = 1.f / l1;
        float* O0 = g_attn + (size_t)(b * TT + t0) * HIDD + h * HDD;
        float* O1 = g_attn + (size_t)(b * TT + t1) * HIDD + h * HDD;
#pragma unroll
        for (int n = 0; n < 16; n++) {
            int d = n * 8 + tg * 2;
            *(float2*)&O0[d] = make_float2(rtf(oacc[n][0] * i0), rtf(oacc[n][1] * i0));
            *(float2*)&O1[d] = make_float2(rtf(oacc[n][2] * i1), rtf(oacc[n][3] * i1));
        }
    }
}

// ---------------------------------------------------------------------------
extern "C" void kernel_launch(void* const* d_in, const int* in_sizes, int n_in,
                              void* d_out, int out_size)
{
    (void)in_sizes; (void)n_in; (void)out_size;
    const float* x      = (const float*)d_in[0];
    const float* w_qkv  = (const float*)d_in[1];
    const float* w_proj = (const float*)d_in[2];
    const float* b_proj = (const float*)d_in[3];
    const float* cosb   = (const float*)d_in[4];
    const float* sinb   = (const float*)d_in[5];
    float* out = (float*)d_out;

    cudaFuncSetAttribute(attn_kernel,
        cudaFuncAttributeMaxDynamicSharedMemorySize, ATTN_SMEM);
    cudaFuncSetAttribute(gemm_tf32<0>,
        cudaFuncAttributeMaxDynamicSharedMemorySize, GEMM_SMEM);
    cudaFuncSetAttribute(gemm_tf32<1>,
        cudaFuncAttributeMaxDynamicSharedMemorySize, GEMM_SMEM);

    float *gx, *gw1, *gw2;
    cudaGetSymbolAddress((void**)&gx,  g_x);
    cudaGetSymbolAddress((void**)&gw1, g_w1);
    cudaGetSymbolAddress((void**)&gw2, g_w2);

    round_k<<<NX  / 1024, 256>>>(x,      gx);
    round_k<<<NW1 / 1024, 256>>>(w_qkv,  gw1);
    round_k<<<NW2 / 1024, 256>>>(w_proj, gw2);

    dim3 blk(256);
    dim3 g0(NQKV / 128, MTOT / 128);
    gemm_tf32<0><<<g0, blk, GEMM_SMEM>>>(cosb, sinb, nullptr, nullptr);

    dim3 ga(TT / 128, BB * NHH);
    attn_kernel<<<ga, blk, ATTN_SMEM>>>();

    dim3 g1(HIDD / 128, MTOT / 128);
    gemm_tf32<1><<<g1, blk, GEMM_SMEM>>>(nullptr, nullptr, b_proj, out);
}